// round 8
// baseline (speedup 1.0000x reference)
#include <cuda_runtime.h>
#include <math.h>

// Problem constants (fixed by setup_inputs)
#define Bdim 4
#define Sdim 1024
#define Ddim 256
#define Hn   6
#define Hd   64
#define HF   384          // Hn*Hd
#define En   3
#define SENT_END 988      // S - sect - doc
#define SECT_END 1020     // S - doc
#define MAXDEG 256
#define BS  (Bdim*Sdim)   // 4096
#define BSD (BS*Ddim)     // 1048576
#define NBIG 1792         // 4*HF + Ddim  (4 experts layer-1 + blend)
#define LDH  1792         // g_hall row stride
#define LDH1 1536         // g_h1all row stride (4*HF)
#define LDH2 1024         // g_h2all row stride (4*Ddim)
#define ESN  (Bdim*Hn*Sdim)  // 24576 per expert

// ----------------------------- device scratch -----------------------------
__device__ __align__(128) int   g_nbr[BS*MAXDEG];      // CSR neighbor lists (ascending j)
__device__ __align__(128) int   g_cnt[BS*3];           // cumulative counts: <988, <1020, total
__device__ __align__(128) float g_mask[En*BS];         // routing mask per deputy expert
__device__ __align__(128) float g_Bpack[Ddim*NBIG];    // packed B: [W1t m|d0|d1|d2 | bW]
__device__ __align__(128) float g_hall [BS*LDH];       // layer-1 out (4 experts) + blend logits
__device__ __align__(128) float g_h1all[BS*LDH1];      // att1+ELU out, 4 experts
__device__ __align__(128) float g_h2all[BS*LDH2];      // layer-2 out, 4 experts
__device__ __align__(128) float g_es[4*ESN];
__device__ __align__(128) float g_ed[4*ESN];
__device__ __align__(128) float g_s2[4*BS];
__device__ __align__(128) float g_d2[4*BS];
__device__ __align__(128) float g_main[BSD];
__device__ __align__(128) float g_dep3[En*BSD];        // per-deputy att2 outputs
__device__ __align__(128) float g_meanh [Bdim*LDH1];   // column means of g_hall (per b)
__device__ __align__(128) float g_meanh2[Bdim*LDH2];   // column means of g_h2all (per b)
__device__ __align__(128) float g_part[1024];

// ----------------------------- kernels -----------------------------

// one warp per row: compact adjacency row into CSR (preserves ascending j order)
__global__ void k_build_csr(const float* __restrict__ adj) {
    int warp = (blockIdx.x*blockDim.x + threadIdx.x) >> 5;
    int lane = threadIdx.x & 31;
    if (warp >= BS) return;
    const float* row = adj + (size_t)warp * Sdim;
    int cnt = 0, c0 = 0, c1 = 0;
    for (int c = 0; c < Sdim; c += 32) {
        int j = c + lane;
        float v = row[j];
        unsigned m = __ballot_sync(0xffffffffu, v > 0.f);
        if (v > 0.f) {
            int pos = cnt + __popc(m & ((1u << lane) - 1u));
            if (pos < MAXDEG) g_nbr[warp*MAXDEG + pos] = j;
        }
        unsigned msent = __ballot_sync(0xffffffffu, j < SENT_END);
        unsigned msect = __ballot_sync(0xffffffffu, j < SECT_END);
        cnt += __popc(m);
        c0  += __popc(m & msent);
        c1  += __popc(m & msect);
    }
    if (lane == 0) {
        g_cnt[warp*3+0] = c0; g_cnt[warp*3+1] = c1; g_cnt[warp*3+2] = cnt;
    }
}

// one warp per node: router logits; top-2 of 3 == exclude argmin (ties -> larger idx)
__global__ void k_router(const float* __restrict__ x, const float* __restrict__ rw) {
    int warp = (blockIdx.x*blockDim.x + threadIdx.x) >> 5;
    int lane = threadIdx.x & 31;
    if (warp >= BS) return;
    const float* xp = x + (size_t)warp * Ddim;
    float l0 = 0.f, l1 = 0.f, l2 = 0.f;
    for (int d = lane; d < Ddim; d += 32) {
        float v = xp[d];
        l0 += v * rw[d*3+0];
        l1 += v * rw[d*3+1];
        l2 += v * rw[d*3+2];
    }
    for (int o = 16; o; o >>= 1) {
        l0 += __shfl_xor_sync(0xffffffffu, l0, o);
        l1 += __shfl_xor_sync(0xffffffffu, l1, o);
        l2 += __shfl_xor_sync(0xffffffffu, l2, o);
    }
    if (lane == 0) {
        int excl = 0; float mn = l0;
        if (l1 <= mn) { mn = l1; excl = 1; }
        if (l2 <= mn) { mn = l2; excl = 2; }
        g_mask[0*BS + warp] = (excl == 0) ? 0.f : 1.f;
        g_mask[1*BS + warp] = (excl == 1) ? 0.f : 1.f;
        g_mask[2*BS + warp] = (excl == 2) ? 0.f : 1.f;
    }
}

// build packed B [D=256 rows][NBIG=1792 cols]:
// cols [e*384 + hh*64 + o] = W1[e][hh][f][o] transposed; cols [1536+d] = bW[f][d]
__global__ void k_pack(const float* __restrict__ mW1, const float* __restrict__ dW1,
                       const float* __restrict__ bW) {
    int i = blockIdx.x*blockDim.x + threadIdx.x;
    if (i >= Ddim*NBIG) return;
    int f   = i / NBIG;
    int col = i - f*NBIG;
    float v;
    if (col < 4*HF) {
        int e  = col / HF;
        int ho = col - e*HF;
        int hh = ho >> 6, o = ho & 63;
        const float* src = (e == 0) ? mW1 : (dW1 + (size_t)(e-1)*Hn*Ddim*Hd);
        v = src[(hh*Ddim + f)*Hd + o];
    } else {
        v = bW[f*Ddim + (col - 4*HF)];
    }
    g_Bpack[i] = v;
}

// ---------------------------------------------------------------------------
// Fused big SGEMM: g_hall[4096,1792] = feature[4096,256] @ g_Bpack[256,1792]
// Tile 128x128, 256 threads, 8Mx8N micro-tile (64 FMA per 4 LDS.128).
// Column tiles: bx 0-2 main, 3-5 dep0, 6-8 dep1, 9-11 dep2, 12-13 blend.
// ---------------------------------------------------------------------------
__global__ void __launch_bounds__(256) k_gemm_big(const float* __restrict__ A) {
    __shared__ __align__(16) float As[16][136];
    __shared__ __align__(16) float Bs[16][128];
    int tid = threadIdx.x;
    int tx = tid & 15;   // N micro (x8)
    int ty = tid >> 4;   // M micro (x8)
    int bx = blockIdx.x; // N tile (0..13)
    int by = blockIdx.y; // M tile (0..31)
    const float* rowmask = nullptr;
    int seg = bx / 3;    // 384 = 3*128, boundaries align with 128-col tiles
    if (bx < 12 && seg > 0) rowmask = g_mask + (size_t)(seg-1)*BS;

    const float* Ab = A + (size_t)by*128*Ddim;
    const float* Bb = g_Bpack + bx*128;
    float acc[8][8];
    #pragma unroll
    for (int i = 0; i < 8; i++)
        #pragma unroll
        for (int j = 0; j < 8; j++) acc[i][j] = 0.f;

    for (int k0 = 0; k0 < Ddim; k0 += 16) {
        #pragma unroll
        for (int l = 0; l < 2; l++) {
            int q  = tid + l*256;         // 512 float4 cover A 128x16
            int r  = q >> 2;
            int c4 = q & 3;
            float4 v = *(const float4*)(Ab + (size_t)r*Ddim + k0 + c4*4);
            As[c4*4+0][r] = v.x; As[c4*4+1][r] = v.y;
            As[c4*4+2][r] = v.z; As[c4*4+3][r] = v.w;
        }
        #pragma unroll
        for (int l = 0; l < 2; l++) {
            int q  = tid + l*256;         // 512 float4 cover B 16x128
            int r  = q >> 5;
            int c4 = q & 31;
            float4 v = *(const float4*)(Bb + (size_t)(k0 + r)*NBIG + c4*4);
            *(float4*)&Bs[r][c4*4] = v;
        }
        __syncthreads();
        #pragma unroll
        for (int k = 0; k < 16; k++) {
            float4 a0 = *(const float4*)&As[k][ty*8];
            float4 a1 = *(const float4*)&As[k][ty*8+4];
            float4 b0 = *(const float4*)&Bs[k][tx*8];
            float4 b1 = *(const float4*)&Bs[k][tx*8+4];
            float a[8] = {a0.x,a0.y,a0.z,a0.w,a1.x,a1.y,a1.z,a1.w};
            float b[8] = {b0.x,b0.y,b0.z,b0.w,b1.x,b1.y,b1.z,b1.w};
            #pragma unroll
            for (int i = 0; i < 8; i++)
                #pragma unroll
                for (int j = 0; j < 8; j++) acc[i][j] += a[i]*b[j];
        }
        __syncthreads();
    }
    #pragma unroll
    for (int i = 0; i < 8; i++) {
        int row = by*128 + ty*8 + i;
        float mv = rowmask ? rowmask[row] : 1.f;
        float* cp = g_hall + (size_t)row*LDH + bx*128 + tx*8;
        float4 v0 = make_float4(acc[i][0]*mv, acc[i][1]*mv, acc[i][2]*mv, acc[i][3]*mv);
        float4 v1 = make_float4(acc[i][4]*mv, acc[i][5]*mv, acc[i][6]*mv, acc[i][7]*mv);
        *(float4*)(cp)     = v0;
        *(float4*)(cp + 4) = v1;
    }
}

// ---------------------------------------------------------------------------
// Batched layer-2 SGEMM over blockIdx.z = expert (0=main, 1..3 deputies):
// g_h2all[:, z*256:(z+1)*256] = g_h1all[:, z*384:(z+1)*384] @ W2_z[384,256]
// Tile 128x128, 8Mx8N micro-tile.
// ---------------------------------------------------------------------------
__global__ void __launch_bounds__(256) k_gemm2(const float* __restrict__ mW2,
                                               const float* __restrict__ dW2) {
    __shared__ __align__(16) float As[16][136];
    __shared__ __align__(16) float Bs[16][128];
    int tid = threadIdx.x;
    int tx = tid & 15;
    int ty = tid >> 4;
    int bx = blockIdx.x;  // 0..1 (N=256)
    int by = blockIdx.y;  // 0..31
    int z  = blockIdx.z;  // expert
    const float* Ap = g_h1all + (size_t)z*HF;                          // lda = LDH1
    const float* Bp = (z == 0) ? mW2 : (dW2 + (size_t)(z-1)*HF*Ddim);  // ldb = 256
    const float* Ab = Ap + (size_t)by*128*LDH1;
    const float* Bb = Bp + bx*128;

    float acc[8][8];
    #pragma unroll
    for (int i = 0; i < 8; i++)
        #pragma unroll
        for (int j = 0; j < 8; j++) acc[i][j] = 0.f;

    for (int k0 = 0; k0 < HF; k0 += 16) {
        #pragma unroll
        for (int l = 0; l < 2; l++) {
            int q  = tid + l*256;
            int r  = q >> 2;
            int c4 = q & 3;
            float4 v = *(const float4*)(Ab + (size_t)r*LDH1 + k0 + c4*4);
            As[c4*4+0][r] = v.x; As[c4*4+1][r] = v.y;
            As[c4*4+2][r] = v.z; As[c4*4+3][r] = v.w;
        }
        #pragma unroll
        for (int l = 0; l < 2; l++) {
            int q  = tid + l*256;
            int r  = q >> 5;
            int c4 = q & 31;
            float4 v = *(const float4*)(Bb + (size_t)(k0 + r)*Ddim + c4*4);
            *(float4*)&Bs[r][c4*4] = v;
        }
        __syncthreads();
        #pragma unroll
        for (int k = 0; k < 16; k++) {
            float4 a0 = *(const float4*)&As[k][ty*8];
            float4 a1 = *(const float4*)&As[k][ty*8+4];
            float4 b0 = *(const float4*)&Bs[k][tx*8];
            float4 b1 = *(const float4*)&Bs[k][tx*8+4];
            float a[8] = {a0.x,a0.y,a0.z,a0.w,a1.x,a1.y,a1.z,a1.w};
            float b[8] = {b0.x,b0.y,b0.z,b0.w,b1.x,b1.y,b1.z,b1.w};
            #pragma unroll
            for (int i = 0; i < 8; i++)
                #pragma unroll
                for (int j = 0; j < 8; j++) acc[i][j] += a[i]*b[j];
        }
        __syncthreads();
    }
    #pragma unroll
    for (int i = 0; i < 8; i++) {
        int row = by*128 + ty*8 + i;
        float* cp = g_h2all + (size_t)row*LDH2 + z*Ddim + bx*128 + tx*8;
        *(float4*)(cp)     = make_float4(acc[i][0], acc[i][1], acc[i][2], acc[i][3]);
        *(float4*)(cp + 4) = make_float4(acc[i][4], acc[i][5], acc[i][6], acc[i][7]);
    }
}

// batched es/ed projections for all 4 experts
__global__ void k_esed4(const float* __restrict__ ma1s, const float* __restrict__ ma1d,
                        const float* __restrict__ da1s, const float* __restrict__ da1d) {
    int idx = blockIdx.x*blockDim.x + threadIdx.x;
    if (idx >= 4*ESN) return;
    int e = idx / ESN;
    int r = idx - e*ESN;
    int s  = r & (Sdim-1);
    int bh = r >> 10;
    int hh = bh % Hn;
    int b  = bh / Hn;
    const float* hp = g_hall + (size_t)(b*Sdim + s)*LDH + e*HF + hh*Hd;
    const float* as = ((e == 0) ? ma1s : da1s + (e-1)*Hn*Hd) + hh*Hd;
    const float* ad = ((e == 0) ? ma1d : da1d + (e-1)*Hn*Hd) + hh*Hd;
    float x = 0.f, y = 0.f;
    #pragma unroll 8
    for (int o = 0; o < Hd; o++) { float v = hp[o]; x += v*as[o]; y += v*ad[o]; }
    g_es[idx] = x; g_ed[idx] = y;
}

// generic per-batch column mean: out[b*cols + c] = mean_r X[(b*Sdim + r)*ldx + c]
__global__ void k_colmean(const float* __restrict__ X, int ldx, int cols, float* __restrict__ out) {
    int idx = blockIdx.x*blockDim.x + threadIdx.x;
    if (idx >= Bdim*cols) return;
    int b = idx / cols, cc = idx - b*cols;
    const float* p = X + (size_t)b*Sdim*ldx + cc;
    float a0 = 0.f, a1 = 0.f, a2 = 0.f, a3 = 0.f;
    for (int r = 0; r < Sdim; r += 4) {
        a0 += p[(size_t)r*ldx];
        a1 += p[(size_t)(r+1)*ldx];
        a2 += p[(size_t)(r+2)*ldx];
        a3 += p[(size_t)(r+3)*ldx];
    }
    out[idx] = (a0 + a1 + a2 + a3) * (1.f/(float)Sdim);
}

// layer-1 sparse attention + ELU, batched: blockIdx.y = 0 main, 1..3 deputy
__global__ void __launch_bounds__(384) k_att1(void) {
    int row = blockIdx.x;
    int ee  = blockIdx.y;
    int b = row >> 10, s = row & 1023;
    __shared__ float sc[Hn][MAXDEG];
    __shared__ int   snbr[MAXDEG];
    __shared__ float sden[Hn];
    const int* c = g_cnt + row*3;
    int lo = 0, hi;
    if      (ee == 0) hi = c[2];
    else if (ee == 1) hi = c[0];
    else if (ee == 2) { lo = c[0]; hi = c[1]; }
    else              { lo = c[1]; hi = c[2]; }
    int deg = hi - lo;
    int tid = threadIdx.x;
    if (deg == 0) {  // all scores -1e9 -> uniform attention over all S -> column mean
        for (int o = tid; o < HF; o += 384) {
            float v = g_meanh[b*LDH1 + ee*HF + o];
            g_h1all[(size_t)row*LDH1 + ee*HF + o] = (v > 0.f) ? v : expm1f(v);
        }
        return;
    }
    for (int j = tid; j < deg; j += 384) snbr[j] = g_nbr[row*MAXDEG + lo + j];
    __syncthreads();
    const float* esb = g_es + ee*ESN + b*Hn*Sdim;
    const float* edb = g_ed + ee*ESN + b*Hn*Sdim;
    for (int idx = tid; idx < Hn*deg; idx += 384) {
        int hh = idx / deg;
        int j  = idx - hh*deg;
        float v = esb[hh*Sdim + s] + edb[hh*Sdim + snbr[j]];
        sc[hh][j] = (v > 0.f) ? v : 0.2f*v;
    }
    __syncthreads();
    int warp = tid >> 5, lane = tid & 31;
    if (warp < Hn) {
        float m = -1e30f;
        for (int j = lane; j < deg; j += 32) m = fmaxf(m, sc[warp][j]);
        for (int o = 16; o; o >>= 1) m = fmaxf(m, __shfl_xor_sync(0xffffffffu, m, o));
        float su = 0.f;
        for (int j = lane; j < deg; j += 32) { float e = expf(sc[warp][j] - m); sc[warp][j] = e; su += e; }
        for (int o = 16; o; o >>= 1) su += __shfl_xor_sync(0xffffffffu, su, o);
        if (lane == 0) sden[warp] = su;
    }
    __syncthreads();
    int hh = tid >> 6, o = tid & 63;
    const float* hb = g_hall + (size_t)(b*Sdim)*LDH + ee*HF + hh*Hd + o;
    float acc0 = 0.f, acc1 = 0.f;
    int j = 0;
    for (; j + 1 < deg; j += 2) {
        acc0 += sc[hh][j]   * hb[(size_t)snbr[j]*LDH];
        acc1 += sc[hh][j+1] * hb[(size_t)snbr[j+1]*LDH];
    }
    if (j < deg) acc0 += sc[hh][j] * hb[(size_t)snbr[j]*LDH];
    float v = (acc0 + acc1) / sden[hh];
    g_h1all[(size_t)row*LDH1 + ee*HF + hh*Hd + o] = (v > 0.f) ? v : expm1f(v);
}

// batched layer-2 attention projections
__global__ void k_s2d24(const float* __restrict__ ma2s, const float* __restrict__ ma2d,
                        const float* __restrict__ da2s, const float* __restrict__ da2d) {
    int idx = blockIdx.x*blockDim.x + threadIdx.x;
    if (idx >= 4*BS) return;
    int e   = idx / BS;
    int row = idx - e*BS;
    const float* p  = g_h2all + (size_t)row*LDH2 + e*Ddim;
    const float* as = (e == 0) ? ma2s : da2s + (e-1)*Ddim;
    const float* ad = (e == 0) ? ma2d : da2d + (e-1)*Ddim;
    float x = 0.f, y = 0.f;
    #pragma unroll 8
    for (int d = 0; d < Ddim; d++) { float v = p[d]; x += v*as[d]; y += v*ad[d]; }
    g_s2[idx] = x; g_d2[idx] = y;
}

// layer-2 sparse attention, batched: y=0 main -> g_main; y=1..3 -> g_dep3[e]
__global__ void __launch_bounds__(256) k_att2(void) {
    int row = blockIdx.x;
    int ee  = blockIdx.y;
    if (ee > 0 && g_mask[(ee-1)*BS + row] == 0.f) return;  // output masked anyway
    int b = row >> 10;
    __shared__ float sc[MAXDEG];
    __shared__ int   snbr[MAXDEG];
    __shared__ float sden;
    const int* c = g_cnt + row*3;
    int lo = 0, hi;
    if      (ee == 0) hi = c[2];
    else if (ee == 1) hi = c[0];
    else if (ee == 2) { lo = c[0]; hi = c[1]; }
    else              { lo = c[1]; hi = c[2]; }
    int deg = hi - lo;
    int tid = threadIdx.x;
    float* outp = (ee == 0) ? (g_main + (size_t)row*Ddim)
                            : (g_dep3 + (size_t)(ee-1)*BSD + (size_t)row*Ddim);
    if (deg == 0) {
        for (int o = tid; o < Ddim; o += 256)
            outp[o] = g_meanh2[b*LDH2 + ee*Ddim + o];
        return;
    }
    for (int j = tid; j < deg; j += 256) snbr[j] = g_nbr[row*MAXDEG + lo + j];
    __syncthreads();
    float srcsc = g_s2[ee*BS + row];
    const float* d2b = g_d2 + ee*BS + b*Sdim;
    for (int j = tid; j < deg; j += 256) {
        float v = srcsc + d2b[snbr[j]];
        sc[j] = (v > 0.f) ? v : 0.2f*v;
    }
    __syncthreads();
    if (tid < 32) {
        float m = -1e30f;
        for (int j = tid; j < deg; j += 32) m = fmaxf(m, sc[j]);
        for (int o = 16; o; o >>= 1) m = fmaxf(m, __shfl_xor_sync(0xffffffffu, m, o));
        float su = 0.f;
        for (int j = tid; j < deg; j += 32) { float e = expf(sc[j] - m); sc[j] = e; su += e; }
        for (int o = 16; o; o >>= 1) su += __shfl_xor_sync(0xffffffffu, su, o);
        if (tid == 0) sden = su;
    }
    __syncthreads();
    const float* hb = g_h2all + (size_t)(b*Sdim)*LDH2 + ee*Ddim + tid;
    float acc0 = 0.f, acc1 = 0.f;
    int j = 0;
    for (; j + 1 < deg; j += 2) {
        acc0 += sc[j]   * hb[(size_t)snbr[j]*LDH2];
        acc1 += sc[j+1] * hb[(size_t)snbr[j+1]*LDH2];
    }
    if (j < deg) acc0 += sc[j] * hb[(size_t)snbr[j]*LDH2];
    outp[tid] = (acc0 + acc1) / sden;
}

// blend + final output + deterministic partial sums of blend weights
__global__ void __launch_bounds__(256) k_final(const float* __restrict__ bbias, float* __restrict__ out) {
    __shared__ float red[256];
    int t = threadIdx.x;
    int base = blockIdx.x*1024;
    float s = 0.f;
    #pragma unroll
    for (int l = 0; l < 4; l++) {
        int i   = base + l*256 + t;
        int row = i >> 8;
        int d   = i & (Ddim-1);
        float blendv = g_hall[(size_t)row*LDH + 4*HF + d];
        float w = 1.f / (1.f + expf(-(blendv + bbias[d])));
        float dep = g_mask[0*BS + row] * g_dep3[0*BSD + i]
                  + g_mask[1*BS + row] * g_dep3[1*BSD + i]
                  + g_mask[2*BS + row] * g_dep3[2*BSD + i];
        out[i] = w*g_main[i] + (1.f - w)*dep;
        s += w;
    }
    red[t] = s; __syncthreads();
    for (int o = 128; o; o >>= 1) { if (t < o) red[t] += red[t+o]; __syncthreads(); }
    if (t == 0) g_part[blockIdx.x] = red[0];
}

__global__ void k_scalar(float* __restrict__ out) {
    __shared__ float red[256];
    int t = threadIdx.x;
    float s = 0.f;
    for (int i = t; i < 1024; i += 256) s += g_part[i];
    red[t] = s; __syncthreads();
    for (int o = 128; o; o >>= 1) { if (t < o) red[t] += red[t+o]; __syncthreads(); }
    if (t == 0) {
        float mc = red[0] / (float)BSD;
        out[BSD]     = fabsf(mc - 0.6f) * 0.01f;
        out[BSD + 1] = mc;
    }
}

// ----------------------------- host launcher -----------------------------
extern "C" void kernel_launch(void* const* d_in, const int* in_sizes, int n_in,
                              void* d_out, int out_size) {
    const float* feature = (const float*)d_in[0];
    const float* adj     = (const float*)d_in[1];
    const float* mW1     = (const float*)d_in[2];
    const float* ma1s    = (const float*)d_in[3];
    const float* ma1d    = (const float*)d_in[4];
    const float* mW2     = (const float*)d_in[5];
    const float* ma2s    = (const float*)d_in[6];
    const float* ma2d    = (const float*)d_in[7];
    const float* dW1     = (const float*)d_in[8];
    const float* da1s    = (const float*)d_in[9];
    const float* da1d    = (const float*)d_in[10];
    const float* dW2     = (const float*)d_in[11];
    const float* da2s    = (const float*)d_in[12];
    const float* da2d    = (const float*)d_in[13];
    const float* rW      = (const float*)d_in[14];
    const float* bW      = (const float*)d_in[15];
    const float* bbias   = (const float*)d_in[16];
    float* out = (float*)d_out;

    static float *p_hall = nullptr, *p_h2all, *p_meanh, *p_meanh2;
    if (!p_hall) {
        cudaGetSymbolAddress((void**)&p_hall,   g_hall);
        cudaGetSymbolAddress((void**)&p_h2all,  g_h2all);
        cudaGetSymbolAddress((void**)&p_meanh,  g_meanh);
        cudaGetSymbolAddress((void**)&p_meanh2, g_meanh2);
    }

    k_router   <<<512, 256>>>(feature, rW);
    k_build_csr<<<512, 256>>>(adj);
    k_pack     <<<(Ddim*NBIG + 255)/256, 256>>>(mW1, dW1, bW);

    // fused layer-1 (4 experts) + blend GEMM: 448 CTAs (128x128 tiles)
    k_gemm_big<<<dim3(NBIG/128, BS/128), 256>>>(feature);

    k_esed4  <<<(4*ESN + 255)/256, 256>>>(ma1s, ma1d, da1s, da1d);
    k_colmean<<<(Bdim*LDH1 + 255)/256, 256>>>(p_hall, LDH, LDH1, p_meanh);

    k_att1<<<dim3(BS, 4), 384>>>();

    // batched layer-2 GEMM over 4 experts: 256 CTAs (128x128 tiles)
    k_gemm2<<<dim3(Ddim/128, BS/128, 4), 256>>>(mW2, dW2);

    k_s2d24  <<<(4*BS + 255)/256, 256>>>(ma2s, ma2d, da2s, da2d);
    k_colmean<<<(Bdim*LDH2 + 255)/256, 256>>>(p_h2all, LDH2, LDH2, p_meanh2);

    k_att2<<<dim3(BS, 4), 256>>>();

    k_final<<<1024, 256>>>(bbias, out);
    if (out_size >= BSD + 2) k_scalar<<<1, 256>>>(out);
}

// round 9
// speedup vs baseline: 1.0804x; 1.0804x over previous
#include <cuda_runtime.h>
#include <math.h>

// Problem constants (fixed by setup_inputs)
#define Bdim 4
#define Sdim 1024
#define Ddim 256
#define Hn   6
#define Hd   64
#define HF   384          // Hn*Hd
#define En   3
#define SENT_END 988      // S - sect - doc
#define SECT_END 1020     // S - doc
#define MAXDEG 256
#define BS  (Bdim*Sdim)   // 4096
#define BSD (BS*Ddim)     // 1048576
#define NBIG 1792         // 4*HF + Ddim  (4 experts layer-1 + blend)
#define LDH  1792         // g_hall row stride
#define LDH1 1536         // g_h1all row stride (4*HF)
#define LDH2 1024         // g_h2all row stride (4*Ddim)
#define ESN  (Bdim*Hn*Sdim)  // 24576 per expert

// ----------------------------- device scratch -----------------------------
__device__ __align__(128) int   g_nbr[BS*MAXDEG];      // CSR neighbor lists (ascending j)
__device__ __align__(128) int   g_cnt[BS*3];           // cumulative counts: <988, <1020, total
__device__ __align__(128) float g_mask[En*BS];         // routing mask per deputy expert
__device__ __align__(128) float g_Bpack[Ddim*NBIG];    // packed B: [W1t m|d0|d1|d2 | bW]
__device__ __align__(128) float g_hall [BS*LDH];       // layer-1 out (4 experts) + blend logits
__device__ __align__(128) float g_h1all[BS*LDH1];      // att1+ELU out, 4 experts
__device__ __align__(128) float g_h2all[BS*LDH2];      // layer-2 out, 4 experts
__device__ __align__(128) float g_es[4*ESN];
__device__ __align__(128) float g_ed[4*ESN];
__device__ __align__(128) float g_s2[4*BS];
__device__ __align__(128) float g_d2[4*BS];
__device__ __align__(128) float g_main[BSD];
__device__ __align__(128) float g_dep3[En*BSD];        // per-deputy att2 outputs
__device__ __align__(128) float g_meanh [Bdim*LDH1];   // column means of g_hall (per b)
__device__ __align__(128) float g_meanh2[Bdim*LDH2];   // column means of g_h2all (per b)
__device__ __align__(128) float g_part[1024];

// ----------------------------- kernels -----------------------------

// one warp per row: compact adjacency row into CSR (preserves ascending j order)
__global__ void k_build_csr(const float* __restrict__ adj) {
    int warp = (blockIdx.x*blockDim.x + threadIdx.x) >> 5;
    int lane = threadIdx.x & 31;
    if (warp >= BS) return;
    const float* row = adj + (size_t)warp * Sdim;
    int cnt = 0, c0 = 0, c1 = 0;
    for (int c = 0; c < Sdim; c += 32) {
        int j = c + lane;
        float v = row[j];
        unsigned m = __ballot_sync(0xffffffffu, v > 0.f);
        if (v > 0.f) {
            int pos = cnt + __popc(m & ((1u << lane) - 1u));
            if (pos < MAXDEG) g_nbr[warp*MAXDEG + pos] = j;
        }
        unsigned msent = __ballot_sync(0xffffffffu, j < SENT_END);
        unsigned msect = __ballot_sync(0xffffffffu, j < SECT_END);
        cnt += __popc(m);
        c0  += __popc(m & msent);
        c1  += __popc(m & msect);
    }
    if (lane == 0) {
        g_cnt[warp*3+0] = c0; g_cnt[warp*3+1] = c1; g_cnt[warp*3+2] = cnt;
    }
}

// one warp per node: router logits; top-2 of 3 == exclude argmin (ties -> larger idx)
__global__ void k_router(const float* __restrict__ x, const float* __restrict__ rw) {
    int warp = (blockIdx.x*blockDim.x + threadIdx.x) >> 5;
    int lane = threadIdx.x & 31;
    if (warp >= BS) return;
    const float* xp = x + (size_t)warp * Ddim;
    float l0 = 0.f, l1 = 0.f, l2 = 0.f;
    for (int d = lane; d < Ddim; d += 32) {
        float v = xp[d];
        l0 += v * rw[d*3+0];
        l1 += v * rw[d*3+1];
        l2 += v * rw[d*3+2];
    }
    for (int o = 16; o; o >>= 1) {
        l0 += __shfl_xor_sync(0xffffffffu, l0, o);
        l1 += __shfl_xor_sync(0xffffffffu, l1, o);
        l2 += __shfl_xor_sync(0xffffffffu, l2, o);
    }
    if (lane == 0) {
        int excl = 0; float mn = l0;
        if (l1 <= mn) { mn = l1; excl = 1; }
        if (l2 <= mn) { mn = l2; excl = 2; }
        g_mask[0*BS + warp] = (excl == 0) ? 0.f : 1.f;
        g_mask[1*BS + warp] = (excl == 1) ? 0.f : 1.f;
        g_mask[2*BS + warp] = (excl == 2) ? 0.f : 1.f;
    }
}

// build packed B [D=256 rows][NBIG=1792 cols]:
// cols [e*384 + hh*64 + o] = W1[e][hh][f][o] transposed; cols [1536+d] = bW[f][d]
__global__ void k_pack(const float* __restrict__ mW1, const float* __restrict__ dW1,
                       const float* __restrict__ bW) {
    int i = blockIdx.x*blockDim.x + threadIdx.x;
    if (i >= Ddim*NBIG) return;
    int f   = i / NBIG;
    int col = i - f*NBIG;
    float v;
    if (col < 4*HF) {
        int e  = col / HF;
        int ho = col - e*HF;
        int hh = ho >> 6, o = ho & 63;
        const float* src = (e == 0) ? mW1 : (dW1 + (size_t)(e-1)*Hn*Ddim*Hd);
        v = src[(hh*Ddim + f)*Hd + o];
    } else {
        v = bW[f*Ddim + (col - 4*HF)];
    }
    g_Bpack[i] = v;
}

// ---------------------------------------------------------------------------
// Fused big SGEMM: g_hall[4096,1792] = feature[4096,256] @ g_Bpack[256,1792]
// Tile 128x64, 256 threads, 8Mx4N micro-tile. Double-buffered smem with
// register prefetch: one __syncthreads per k-step, global loads for stage s+1
// issued before the compute of stage s.
// ---------------------------------------------------------------------------
__global__ void __launch_bounds__(256, 3) k_gemm_big(const float* __restrict__ A) {
    __shared__ __align__(16) float As[2][16][128];
    __shared__ __align__(16) float Bs[2][16][64];
    int tid = threadIdx.x;
    int tx = tid & 15;   // N micro (x4)
    int ty = tid >> 4;   // M micro (x8)
    int bx = blockIdx.x; // N tile (0..27)
    int by = blockIdx.y; // M tile (0..31)
    // blocks 0-5: main (no mask), 6-11: dep0, 12-17: dep1, 18-23: dep2, 24-27: blend
    const float* rowmask = nullptr;
    int seg = bx / 6;
    if (bx < 24 && seg > 0) rowmask = g_mask + (size_t)(seg-1)*BS;

    const float* Ab = A + (size_t)by*128*Ddim;
    const float* Bb = g_Bpack + bx*64;

    // load indexing (fixed per thread)
    int r0 = tid >> 2,        c40 = (tid & 3) * 4;        // A float4 #1
    int r1 = (tid + 256) >> 2, c41 = ((tid + 256) & 3) * 4; // A float4 #2
    int rb = tid >> 4,        cb  = (tid & 15) * 4;       // B float4

    float acc[8][4];
    #pragma unroll
    for (int i = 0; i < 8; i++)
        #pragma unroll
        for (int j = 0; j < 4; j++) acc[i][j] = 0.f;

    // ---- stage 0 ----
    {
        float4 va0 = *(const float4*)(Ab + (size_t)r0*Ddim + c40);
        float4 va1 = *(const float4*)(Ab + (size_t)r1*Ddim + c41);
        float4 vb  = *(const float4*)(Bb + (size_t)rb*NBIG + cb);
        As[0][c40+0][r0] = va0.x; As[0][c40+1][r0] = va0.y;
        As[0][c40+2][r0] = va0.z; As[0][c40+3][r0] = va0.w;
        As[0][c41+0][r1] = va1.x; As[0][c41+1][r1] = va1.y;
        As[0][c41+2][r1] = va1.z; As[0][c41+3][r1] = va1.w;
        *(float4*)&Bs[0][rb][cb] = vb;
    }
    __syncthreads();

    const int nstage = Ddim / 16;   // 16
    for (int s = 0; s < nstage; s++) {
        int cur = s & 1, nxt = cur ^ 1;
        float4 pa0, pa1, pb;
        bool has_next = (s + 1 < nstage);
        if (has_next) {
            int kn = (s + 1) * 16;
            pa0 = *(const float4*)(Ab + (size_t)r0*Ddim + kn + c40);
            pa1 = *(const float4*)(Ab + (size_t)r1*Ddim + kn + c41);
            pb  = *(const float4*)(Bb + (size_t)(kn + rb)*NBIG + cb);
        }
        #pragma unroll
        for (int k = 0; k < 16; k++) {
            float4 a0 = *(const float4*)&As[cur][k][ty*8];
            float4 a1 = *(const float4*)&As[cur][k][ty*8+4];
            float4 b0 = *(const float4*)&Bs[cur][k][tx*4];
            float a[8] = {a0.x,a0.y,a0.z,a0.w,a1.x,a1.y,a1.z,a1.w};
            float bb[4] = {b0.x,b0.y,b0.z,b0.w};
            #pragma unroll
            for (int i = 0; i < 8; i++)
                #pragma unroll
                for (int j = 0; j < 4; j++) acc[i][j] += a[i]*bb[j];
        }
        if (has_next) {
            As[nxt][c40+0][r0] = pa0.x; As[nxt][c40+1][r0] = pa0.y;
            As[nxt][c40+2][r0] = pa0.z; As[nxt][c40+3][r0] = pa0.w;
            As[nxt][c41+0][r1] = pa1.x; As[nxt][c41+1][r1] = pa1.y;
            As[nxt][c41+2][r1] = pa1.z; As[nxt][c41+3][r1] = pa1.w;
            *(float4*)&Bs[nxt][rb][cb] = pb;
        }
        __syncthreads();
    }

    #pragma unroll
    for (int i = 0; i < 8; i++) {
        int row = by*128 + ty*8 + i;
        float mv = rowmask ? rowmask[row] : 1.f;
        float* cp = g_hall + (size_t)row*LDH + bx*64 + tx*4;
        cp[0] = acc[i][0]*mv; cp[1] = acc[i][1]*mv;
        cp[2] = acc[i][2]*mv; cp[3] = acc[i][3]*mv;
    }
}

// ---------------------------------------------------------------------------
// Batched layer-2 SGEMM over blockIdx.z = expert (0=main, 1..3 deputies):
// g_h2all[:, z*256:(z+1)*256] = g_h1all[:, z*384:(z+1)*384] @ W2_z[384,256]
// Same double-buffered 128x64 tile.
// ---------------------------------------------------------------------------
__global__ void __launch_bounds__(256, 3) k_gemm2(const float* __restrict__ mW2,
                                                  const float* __restrict__ dW2) {
    __shared__ __align__(16) float As[2][16][128];
    __shared__ __align__(16) float Bs[2][16][64];
    int tid = threadIdx.x;
    int tx = tid & 15;
    int ty = tid >> 4;
    int bx = blockIdx.x;  // 0..3 (N=256)
    int by = blockIdx.y;  // 0..31
    int z  = blockIdx.z;  // expert
    const float* Ap = g_h1all + (size_t)z*HF;                          // lda = LDH1
    const float* Bp = (z == 0) ? mW2 : (dW2 + (size_t)(z-1)*HF*Ddim);  // ldb = 256
    const float* Ab = Ap + (size_t)by*128*LDH1;
    const float* Bb = Bp + bx*64;

    int r0 = tid >> 2,         c40 = (tid & 3) * 4;
    int r1 = (tid + 256) >> 2, c41 = ((tid + 256) & 3) * 4;
    int rb = tid >> 4,         cb  = (tid & 15) * 4;

    float acc[8][4];
    #pragma unroll
    for (int i = 0; i < 8; i++)
        #pragma unroll
        for (int j = 0; j < 4; j++) acc[i][j] = 0.f;

    {
        float4 va0 = *(const float4*)(Ab + (size_t)r0*LDH1 + c40);
        float4 va1 = *(const float4*)(Ab + (size_t)r1*LDH1 + c41);
        float4 vb  = *(const float4*)(Bb + (size_t)rb*Ddim + cb);
        As[0][c40+0][r0] = va0.x; As[0][c40+1][r0] = va0.y;
        As[0][c40+2][r0] = va0.z; As[0][c40+3][r0] = va0.w;
        As[0][c41+0][r1] = va1.x; As[0][c41+1][r1] = va1.y;
        As[0][c41+2][r1] = va1.z; As[0][c41+3][r1] = va1.w;
        *(float4*)&Bs[0][rb][cb] = vb;
    }
    __syncthreads();

    const int nstage = HF / 16;   // 24
    for (int s = 0; s < nstage; s++) {
        int cur = s & 1, nxt = cur ^ 1;
        float4 pa0, pa1, pb;
        bool has_next = (s + 1 < nstage);
        if (has_next) {
            int kn = (s + 1) * 16;
            pa0 = *(const float4*)(Ab + (size_t)r0*LDH1 + kn + c40);
            pa1 = *(const float4*)(Ab + (size_t)r1*LDH1 + kn + c41);
            pb  = *(const float4*)(Bb + (size_t)(kn + rb)*Ddim + cb);
        }
        #pragma unroll
        for (int k = 0; k < 16; k++) {
            float4 a0 = *(const float4*)&As[cur][k][ty*8];
            float4 a1 = *(const float4*)&As[cur][k][ty*8+4];
            float4 b0 = *(const float4*)&Bs[cur][k][tx*4];
            float a[8] = {a0.x,a0.y,a0.z,a0.w,a1.x,a1.y,a1.z,a1.w};
            float bb[4] = {b0.x,b0.y,b0.z,b0.w};
            #pragma unroll
            for (int i = 0; i < 8; i++)
                #pragma unroll
                for (int j = 0; j < 4; j++) acc[i][j] += a[i]*bb[j];
        }
        if (has_next) {
            As[nxt][c40+0][r0] = pa0.x; As[nxt][c40+1][r0] = pa0.y;
            As[nxt][c40+2][r0] = pa0.z; As[nxt][c40+3][r0] = pa0.w;
            As[nxt][c41+0][r1] = pa1.x; As[nxt][c41+1][r1] = pa1.y;
            As[nxt][c41+2][r1] = pa1.z; As[nxt][c41+3][r1] = pa1.w;
            *(float4*)&Bs[nxt][rb][cb] = pb;
        }
        __syncthreads();
    }

    #pragma unroll
    for (int i = 0; i < 8; i++) {
        int row = by*128 + ty*8 + i;
        float* cp = g_h2all + (size_t)row*LDH2 + z*Ddim + bx*64 + tx*4;
        cp[0] = acc[i][0]; cp[1] = acc[i][1];
        cp[2] = acc[i][2]; cp[3] = acc[i][3];
    }
}

// batched es/ed projections for all 4 experts
__global__ void k_esed4(const float* __restrict__ ma1s, const float* __restrict__ ma1d,
                        const float* __restrict__ da1s, const float* __restrict__ da1d) {
    int idx = blockIdx.x*blockDim.x + threadIdx.x;
    if (idx >= 4*ESN) return;
    int e = idx / ESN;
    int r = idx - e*ESN;
    int s  = r & (Sdim-1);
    int bh = r >> 10;
    int hh = bh % Hn;
    int b  = bh / Hn;
    const float* hp = g_hall + (size_t)(b*Sdim + s)*LDH + e*HF + hh*Hd;
    const float* as = ((e == 0) ? ma1s : da1s + (e-1)*Hn*Hd) + hh*Hd;
    const float* ad = ((e == 0) ? ma1d : da1d + (e-1)*Hn*Hd) + hh*Hd;
    float x = 0.f, y = 0.f;
    #pragma unroll 8
    for (int o = 0; o < Hd; o++) { float v = hp[o]; x += v*as[o]; y += v*ad[o]; }
    g_es[idx] = x; g_ed[idx] = y;
}

// generic per-batch column mean: out[b*cols + c] = mean_r X[(b*Sdim + r)*ldx + c]
__global__ void k_colmean(const float* __restrict__ X, int ldx, int cols, float* __restrict__ out) {
    int idx = blockIdx.x*blockDim.x + threadIdx.x;
    if (idx >= Bdim*cols) return;
    int b = idx / cols, cc = idx - b*cols;
    const float* p = X + (size_t)b*Sdim*ldx + cc;
    float a0 = 0.f, a1 = 0.f, a2 = 0.f, a3 = 0.f;
    for (int r = 0; r < Sdim; r += 4) {
        a0 += p[(size_t)r*ldx];
        a1 += p[(size_t)(r+1)*ldx];
        a2 += p[(size_t)(r+2)*ldx];
        a3 += p[(size_t)(r+3)*ldx];
    }
    out[idx] = (a0 + a1 + a2 + a3) * (1.f/(float)Sdim);
}

// layer-1 sparse attention + ELU, batched: blockIdx.y = 0 main, 1..3 deputy
__global__ void __launch_bounds__(384) k_att1(void) {
    int row = blockIdx.x;
    int ee  = blockIdx.y;
    int b = row >> 10, s = row & 1023;
    __shared__ float sc[Hn][MAXDEG];
    __shared__ int   snbr[MAXDEG];
    __shared__ float sden[Hn];
    const int* c = g_cnt + row*3;
    int lo = 0, hi;
    if      (ee == 0) hi = c[2];
    else if (ee == 1) hi = c[0];
    else if (ee == 2) { lo = c[0]; hi = c[1]; }
    else              { lo = c[1]; hi = c[2]; }
    int deg = hi - lo;
    int tid = threadIdx.x;
    if (deg == 0) {  // all scores -1e9 -> uniform attention over all S -> column mean
        for (int o = tid; o < HF; o += 384) {
            float v = g_meanh[b*LDH1 + ee*HF + o];
            g_h1all[(size_t)row*LDH1 + ee*HF + o] = (v > 0.f) ? v : expm1f(v);
        }
        return;
    }
    for (int j = tid; j < deg; j += 384) snbr[j] = g_nbr[row*MAXDEG + lo + j];
    __syncthreads();
    const float* esb = g_es + ee*ESN + b*Hn*Sdim;
    const float* edb = g_ed + ee*ESN + b*Hn*Sdim;
    for (int idx = tid; idx < Hn*deg; idx += 384) {
        int hh = idx / deg;
        int j  = idx - hh*deg;
        float v = esb[hh*Sdim + s] + edb[hh*Sdim + snbr[j]];
        sc[hh][j] = (v > 0.f) ? v : 0.2f*v;
    }
    __syncthreads();
    int warp = tid >> 5, lane = tid & 31;
    if (warp < Hn) {
        float m = -1e30f;
        for (int j = lane; j < deg; j += 32) m = fmaxf(m, sc[warp][j]);
        for (int o = 16; o; o >>= 1) m = fmaxf(m, __shfl_xor_sync(0xffffffffu, m, o));
        float su = 0.f;
        for (int j = lane; j < deg; j += 32) { float e = expf(sc[warp][j] - m); sc[warp][j] = e; su += e; }
        for (int o = 16; o; o >>= 1) su += __shfl_xor_sync(0xffffffffu, su, o);
        if (lane == 0) sden[warp] = su;
    }
    __syncthreads();
    int hh = tid >> 6, o = tid & 63;
    const float* hb = g_hall + (size_t)(b*Sdim)*LDH + ee*HF + hh*Hd + o;
    float acc0 = 0.f, acc1 = 0.f;
    int j = 0;
    for (; j + 1 < deg; j += 2) {
        acc0 += sc[hh][j]   * hb[(size_t)snbr[j]*LDH];
        acc1 += sc[hh][j+1] * hb[(size_t)snbr[j+1]*LDH];
    }
    if (j < deg) acc0 += sc[hh][j] * hb[(size_t)snbr[j]*LDH];
    float v = (acc0 + acc1) / sden[hh];
    g_h1all[(size_t)row*LDH1 + ee*HF + hh*Hd + o] = (v > 0.f) ? v : expm1f(v);
}

// batched layer-2 attention projections
__global__ void k_s2d24(const float* __restrict__ ma2s, const float* __restrict__ ma2d,
                        const float* __restrict__ da2s, const float* __restrict__ da2d) {
    int idx = blockIdx.x*blockDim.x + threadIdx.x;
    if (idx >= 4*BS) return;
    int e   = idx / BS;
    int row = idx - e*BS;
    const float* p  = g_h2all + (size_t)row*LDH2 + e*Ddim;
    const float* as = (e == 0) ? ma2s : da2s + (e-1)*Ddim;
    const float* ad = (e == 0) ? ma2d : da2d + (e-1)*Ddim;
    float x = 0.f, y = 0.f;
    #pragma unroll 8
    for (int d = 0; d < Ddim; d++) { float v = p[d]; x += v*as[d]; y += v*ad[d]; }
    g_s2[idx] = x; g_d2[idx] = y;
}

// layer-2 sparse attention, batched: y=0 main -> g_main; y=1..3 -> g_dep3[e]
__global__ void __launch_bounds__(256) k_att2(void) {
    int row = blockIdx.x;
    int ee  = blockIdx.y;
    if (ee > 0 && g_mask[(ee-1)*BS + row] == 0.f) return;  // output masked anyway
    int b = row >> 10;
    __shared__ float sc[MAXDEG];
    __shared__ int   snbr[MAXDEG];
    __shared__ float sden;
    const int* c = g_cnt + row*3;
    int lo = 0, hi;
    if      (ee == 0) hi = c[2];
    else if (ee == 1) hi = c[0];
    else if (ee == 2) { lo = c[0]; hi = c[1]; }
    else              { lo = c[1]; hi = c[2]; }
    int deg = hi - lo;
    int tid = threadIdx.x;
    float* outp = (ee == 0) ? (g_main + (size_t)row*Ddim)
                            : (g_dep3 + (size_t)(ee-1)*BSD + (size_t)row*Ddim);
    if (deg == 0) {
        for (int o = tid; o < Ddim; o += 256)
            outp[o] = g_meanh2[b*LDH2 + ee*Ddim + o];
        return;
    }
    for (int j = tid; j < deg; j += 256) snbr[j] = g_nbr[row*MAXDEG + lo + j];
    __syncthreads();
    float srcsc = g_s2[ee*BS + row];
    const float* d2b = g_d2 + ee*BS + b*Sdim;
    for (int j = tid; j < deg; j += 256) {
        float v = srcsc + d2b[snbr[j]];
        sc[j] = (v > 0.f) ? v : 0.2f*v;
    }
    __syncthreads();
    if (tid < 32) {
        float m = -1e30f;
        for (int j = tid; j < deg; j += 32) m = fmaxf(m, sc[j]);
        for (int o = 16; o; o >>= 1) m = fmaxf(m, __shfl_xor_sync(0xffffffffu, m, o));
        float su = 0.f;
        for (int j = tid; j < deg; j += 32) { float e = expf(sc[j] - m); sc[j] = e; su += e; }
        for (int o = 16; o; o >>= 1) su += __shfl_xor_sync(0xffffffffu, su, o);
        if (tid == 0) sden = su;
    }
    __syncthreads();
    const float* hb = g_h2all + (size_t)(b*Sdim)*LDH2 + ee*Ddim + tid;
    float acc0 = 0.f, acc1 = 0.f;
    int j = 0;
    for (; j + 1 < deg; j += 2) {
        acc0 += sc[j]   * hb[(size_t)snbr[j]*LDH2];
        acc1 += sc[j+1] * hb[(size_t)snbr[j+1]*LDH2];
    }
    if (j < deg) acc0 += sc[j] * hb[(size_t)snbr[j]*LDH2];
    outp[tid] = (acc0 + acc1) / sden;
}

// blend + final output + deterministic partial sums of blend weights
__global__ void __launch_bounds__(256) k_final(const float* __restrict__ bbias, float* __restrict__ out) {
    __shared__ float red[256];
    int t = threadIdx.x;
    int base = blockIdx.x*1024;
    float s = 0.f;
    #pragma unroll
    for (int l = 0; l < 4; l++) {
        int i   = base + l*256 + t;
        int row = i >> 8;
        int d   = i & (Ddim-1);
        float blendv = g_hall[(size_t)row*LDH + 4*HF + d];
        float w = 1.f / (1.f + expf(-(blendv + bbias[d])));
        float dep = g_mask[0*BS + row] * g_dep3[0*BSD + i]
                  + g_mask[1*BS + row] * g_dep3[1*BSD + i]
                  + g_mask[2*BS + row] * g_dep3[2*BSD + i];
        out[i] = w*g_main[i] + (1.f - w)*dep;
        s += w;
    }
    red[t] = s; __syncthreads();
    for (int o = 128; o; o >>= 1) { if (t < o) red[t] += red[t+o]; __syncthreads(); }
    if (t == 0) g_part[blockIdx.x] = red[0];
}

__global__ void k_scalar(float* __restrict__ out) {
    __shared__ float red[256];
    int t = threadIdx.x;
    float s = 0.f;
    for (int i = t; i < 1024; i += 256) s += g_part[i];
    red[t] = s; __syncthreads();
    for (int o = 128; o; o >>= 1) { if (t < o) red[t] += red[t+o]; __syncthreads(); }
    if (t == 0) {
        float mc = red[0] / (float)BSD;
        out[BSD]     = fabsf(mc - 0.6f) * 0.01f;
        out[BSD + 1] = mc;
    }
}

// ----------------------------- host launcher -----------------------------
extern "C" void kernel_launch(void* const* d_in, const int* in_sizes, int n_in,
                              void* d_out, int out_size) {
    const float* feature = (const float*)d_in[0];
    const float* adj     = (const float*)d_in[1];
    const float* mW1     = (const float*)d_in[2];
    const float* ma1s    = (const float*)d_in[3];
    const float* ma1d    = (const float*)d_in[4];
    const float* mW2     = (const float*)d_in[5];
    const float* ma2s    = (const float*)d_in[6];
    const float* ma2d    = (const float*)d_in[7];
    const float* dW1     = (const float*)d_in[8];
    const float* da1s    = (const float*)d_in[9];
    const float* da1d    = (const float*)d_in[10];
    const float* dW2     = (const float*)d_in[11];
    const float* da2s    = (const float*)d_in[12];
    const float* da2d    = (const float*)d_in[13];
    const float* rW      = (const float*)d_in[14];
    const float* bW      = (const float*)d_in[15];
    const float* bbias   = (const float*)d_in[16];
    float* out = (float*)d_out;

    static float *p_hall = nullptr, *p_h2all, *p_meanh, *p_meanh2;
    if (!p_hall) {
        cudaGetSymbolAddress((void**)&p_hall,   g_hall);
        cudaGetSymbolAddress((void**)&p_h2all,  g_h2all);
        cudaGetSymbolAddress((void**)&p_meanh,  g_meanh);
        cudaGetSymbolAddress((void**)&p_meanh2, g_meanh2);
    }

    k_router   <<<512, 256>>>(feature, rW);
    k_build_csr<<<512, 256>>>(adj);
    k_pack     <<<(Ddim*NBIG + 255)/256, 256>>>(mW1, dW1, bW);

    // fused layer-1 (4 experts) + blend GEMM: 896 CTAs (128x64 tiles)
    k_gemm_big<<<dim3(NBIG/64, BS/128), 256>>>(feature);

    k_esed4  <<<(4*ESN + 255)/256, 256>>>(ma1s, ma1d, da1s, da1d);
    k_colmean<<<(Bdim*LDH1 + 255)/256, 256>>>(p_hall, LDH, LDH1, p_meanh);

    k_att1<<<dim3(BS, 4), 384>>>();

    // batched layer-2 GEMM over 4 experts: 512 CTAs (128x64 tiles)
    k_gemm2<<<dim3(Ddim/64, BS/128, 4), 256>>>(mW2, dW2);

    k_s2d24  <<<(4*BS + 255)/256, 256>>>(ma2s, ma2d, da2s, da2d);
    k_colmean<<<(Bdim*LDH2 + 255)/256, 256>>>(p_h2all, LDH2, LDH2, p_meanh2);

    k_att2<<<dim3(BS, 4), 256>>>();

    k_final<<<1024, 256>>>(bbias, out);
    if (out_size >= BSD + 2) k_scalar<<<1, 256>>>(out);
}

// round 11
// speedup vs baseline: 1.1619x; 1.0754x over previous
#include <cuda_runtime.h>
#include <math.h>

// Problem constants (fixed by setup_inputs)
#define Bdim 4
#define Sdim 1024
#define Ddim 256
#define Hn   6
#define Hd   64
#define HF   384          // Hn*Hd
#define En   3
#define SENT_END 988      // S - sect - doc
#define SECT_END 1020     // S - doc
#define MAXDEG 256
#define BS  (Bdim*Sdim)   // 4096
#define BSD (BS*Ddim)     // 1048576
#define NBIG 1792         // 4*HF + Ddim  (4 experts layer-1 + blend)
#define LDH  1792         // g_hall row stride
#define LDH1 1536         // g_h1all row stride (4*HF)
#define LDH2 1024         // g_h2all row stride (4*Ddim)
#define ESN  (Bdim*Hn*Sdim)  // 24576 per expert

// ----------------------------- device scratch -----------------------------
__device__ __align__(128) int   g_nbr[BS*MAXDEG];      // CSR neighbor lists (ascending j)
__device__ __align__(128) int   g_cnt[BS*3];           // cumulative counts: <988, <1020, total
__device__ __align__(128) float g_mask[En*BS];         // routing mask per deputy expert
__device__ __align__(128) float g_Bpack[Ddim*NBIG];    // packed B: [W1t m|d0|d1|d2 | bW]
__device__ __align__(128) float g_hall [BS*LDH];       // layer-1 out (4 experts) + blend logits
__device__ __align__(128) float g_h1all[BS*LDH1];      // att1+ELU out, 4 experts
__device__ __align__(128) float g_h2all[BS*LDH2];      // layer-2 out, 4 experts
__device__ __align__(128) float g_es[4*ESN];
__device__ __align__(128) float g_ed[4*ESN];
__device__ __align__(128) float g_s2[4*BS];
__device__ __align__(128) float g_d2[4*BS];
__device__ __align__(128) float g_main[BSD];
__device__ __align__(128) float g_dep3[En*BSD];        // per-deputy att2 outputs
__device__ __align__(128) float g_meanh [Bdim*LDH1];   // column means of g_hall (per b)
__device__ __align__(128) float g_meanh2[Bdim*LDH2];   // column means of g_h2all (per b)
__device__ __align__(128) float g_part[1024];

// ----------------------------- kernels -----------------------------

// one warp per row: compact adjacency row into CSR (preserves ascending j order)
__global__ void k_build_csr(const float* __restrict__ adj) {
    int warp = (blockIdx.x*blockDim.x + threadIdx.x) >> 5;
    int lane = threadIdx.x & 31;
    if (warp >= BS) return;
    const float* row = adj + (size_t)warp * Sdim;
    int cnt = 0, c0 = 0, c1 = 0;
    for (int c = 0; c < Sdim; c += 32) {
        int j = c + lane;
        float v = row[j];
        unsigned m = __ballot_sync(0xffffffffu, v > 0.f);
        if (v > 0.f) {
            int pos = cnt + __popc(m & ((1u << lane) - 1u));
            if (pos < MAXDEG) g_nbr[warp*MAXDEG + pos] = j;
        }
        unsigned msent = __ballot_sync(0xffffffffu, j < SENT_END);
        unsigned msect = __ballot_sync(0xffffffffu, j < SECT_END);
        cnt += __popc(m);
        c0  += __popc(m & msent);
        c1  += __popc(m & msect);
    }
    if (lane == 0) {
        g_cnt[warp*3+0] = c0; g_cnt[warp*3+1] = c1; g_cnt[warp*3+2] = cnt;
    }
}

// one warp per node: router logits; top-2 of 3 == exclude argmin (ties -> larger idx)
__global__ void k_router(const float* __restrict__ x, const float* __restrict__ rw) {
    int warp = (blockIdx.x*blockDim.x + threadIdx.x) >> 5;
    int lane = threadIdx.x & 31;
    if (warp >= BS) return;
    const float* xp = x + (size_t)warp * Ddim;
    float l0 = 0.f, l1 = 0.f, l2 = 0.f;
    for (int d = lane; d < Ddim; d += 32) {
        float v = xp[d];
        l0 += v * rw[d*3+0];
        l1 += v * rw[d*3+1];
        l2 += v * rw[d*3+2];
    }
    for (int o = 16; o; o >>= 1) {
        l0 += __shfl_xor_sync(0xffffffffu, l0, o);
        l1 += __shfl_xor_sync(0xffffffffu, l1, o);
        l2 += __shfl_xor_sync(0xffffffffu, l2, o);
    }
    if (lane == 0) {
        int excl = 0; float mn = l0;
        if (l1 <= mn) { mn = l1; excl = 1; }
        if (l2 <= mn) { mn = l2; excl = 2; }
        g_mask[0*BS + warp] = (excl == 0) ? 0.f : 1.f;
        g_mask[1*BS + warp] = (excl == 1) ? 0.f : 1.f;
        g_mask[2*BS + warp] = (excl == 2) ? 0.f : 1.f;
    }
}

// build packed B [D=256 rows][NBIG=1792 cols]:
// cols [e*384 + hh*64 + o] = W1[e][hh][f][o] transposed; cols [1536+d] = bW[f][d]
__global__ void k_pack(const float* __restrict__ mW1, const float* __restrict__ dW1,
                       const float* __restrict__ bW) {
    int i = blockIdx.x*blockDim.x + threadIdx.x;
    if (i >= Ddim*NBIG) return;
    int f   = i / NBIG;
    int col = i - f*NBIG;
    float v;
    if (col < 4*HF) {
        int e  = col / HF;
        int ho = col - e*HF;
        int hh = ho >> 6, o = ho & 63;
        const float* src = (e == 0) ? mW1 : (dW1 + (size_t)(e-1)*Hn*Ddim*Hd);
        v = src[(hh*Ddim + f)*Hd + o];
    } else {
        v = bW[f*Ddim + (col - 4*HF)];
    }
    g_Bpack[i] = v;
}

// ---------------------------------------------------------------------------
// Fused big SGEMM: g_hall[4096,1792] = feature[4096,256] @ g_Bpack[256,1792]
// Tile 128x64, 256 threads, 8Mx4N micro-tile, double-buffered smem.
// ---------------------------------------------------------------------------
__global__ void __launch_bounds__(256, 3) k_gemm_big(const float* __restrict__ A) {
    __shared__ __align__(16) float As[2][16][128];
    __shared__ __align__(16) float Bs[2][16][64];
    int tid = threadIdx.x;
    int tx = tid & 15;   // N micro (x4)
    int ty = tid >> 4;   // M micro (x8)
    int bx = blockIdx.x; // N tile (0..27)
    int by = blockIdx.y; // M tile (0..31)
    const float* rowmask = nullptr;
    int seg = bx / 6;
    if (bx < 24 && seg > 0) rowmask = g_mask + (size_t)(seg-1)*BS;

    const float* Ab = A + (size_t)by*128*Ddim;
    const float* Bb = g_Bpack + bx*64;

    int r0 = tid >> 2,         c40 = (tid & 3) * 4;
    int r1 = (tid + 256) >> 2, c41 = ((tid + 256) & 3) * 4;
    int rb = tid >> 4,         cb  = (tid & 15) * 4;

    float acc[8][4];
    #pragma unroll
    for (int i = 0; i < 8; i++)
        #pragma unroll
        for (int j = 0; j < 4; j++) acc[i][j] = 0.f;

    {
        float4 va0 = *(const float4*)(Ab + (size_t)r0*Ddim + c40);
        float4 va1 = *(const float4*)(Ab + (size_t)r1*Ddim + c41);
        float4 vb  = *(const float4*)(Bb + (size_t)rb*NBIG + cb);
        As[0][c40+0][r0] = va0.x; As[0][c40+1][r0] = va0.y;
        As[0][c40+2][r0] = va0.z; As[0][c40+3][r0] = va0.w;
        As[0][c41+0][r1] = va1.x; As[0][c41+1][r1] = va1.y;
        As[0][c41+2][r1] = va1.z; As[0][c41+3][r1] = va1.w;
        *(float4*)&Bs[0][rb][cb] = vb;
    }
    __syncthreads();

    const int nstage = Ddim / 16;   // 16
    for (int s = 0; s < nstage; s++) {
        int cur = s & 1, nxt = cur ^ 1;
        float4 pa0, pa1, pb;
        bool has_next = (s + 1 < nstage);
        if (has_next) {
            int kn = (s + 1) * 16;
            pa0 = *(const float4*)(Ab + (size_t)r0*Ddim + kn + c40);
            pa1 = *(const float4*)(Ab + (size_t)r1*Ddim + kn + c41);
            pb  = *(const float4*)(Bb + (size_t)(kn + rb)*NBIG + cb);
        }
        #pragma unroll
        for (int k = 0; k < 16; k++) {
            float4 a0 = *(const float4*)&As[cur][k][ty*8];
            float4 a1 = *(const float4*)&As[cur][k][ty*8+4];
            float4 b0 = *(const float4*)&Bs[cur][k][tx*4];
            float a[8] = {a0.x,a0.y,a0.z,a0.w,a1.x,a1.y,a1.z,a1.w};
            float bb[4] = {b0.x,b0.y,b0.z,b0.w};
            #pragma unroll
            for (int i = 0; i < 8; i++)
                #pragma unroll
                for (int j = 0; j < 4; j++) acc[i][j] += a[i]*bb[j];
        }
        if (has_next) {
            As[nxt][c40+0][r0] = pa0.x; As[nxt][c40+1][r0] = pa0.y;
            As[nxt][c40+2][r0] = pa0.z; As[nxt][c40+3][r0] = pa0.w;
            As[nxt][c41+0][r1] = pa1.x; As[nxt][c41+1][r1] = pa1.y;
            As[nxt][c41+2][r1] = pa1.z; As[nxt][c41+3][r1] = pa1.w;
            *(float4*)&Bs[nxt][rb][cb] = pb;
        }
        __syncthreads();
    }

    #pragma unroll
    for (int i = 0; i < 8; i++) {
        int row = by*128 + ty*8 + i;
        float mv = rowmask ? rowmask[row] : 1.f;
        float* cp = g_hall + (size_t)row*LDH + bx*64 + tx*4;
        cp[0] = acc[i][0]*mv; cp[1] = acc[i][1]*mv;
        cp[2] = acc[i][2]*mv; cp[3] = acc[i][3]*mv;
    }
}

// ---------------------------------------------------------------------------
// Batched layer-2 SGEMM over blockIdx.z = expert (0=main, 1..3 deputies)
// ---------------------------------------------------------------------------
__global__ void __launch_bounds__(256, 3) k_gemm2(const float* __restrict__ mW2,
                                                  const float* __restrict__ dW2) {
    __shared__ __align__(16) float As[2][16][128];
    __shared__ __align__(16) float Bs[2][16][64];
    int tid = threadIdx.x;
    int tx = tid & 15;
    int ty = tid >> 4;
    int bx = blockIdx.x;  // 0..3 (N=256)
    int by = blockIdx.y;  // 0..31
    int z  = blockIdx.z;  // expert
    const float* Ap = g_h1all + (size_t)z*HF;                          // lda = LDH1
    const float* Bp = (z == 0) ? mW2 : (dW2 + (size_t)(z-1)*HF*Ddim);  // ldb = 256
    const float* Ab = Ap + (size_t)by*128*LDH1;
    const float* Bb = Bp + bx*64;

    int r0 = tid >> 2,         c40 = (tid & 3) * 4;
    int r1 = (tid + 256) >> 2, c41 = ((tid + 256) & 3) * 4;
    int rb = tid >> 4,         cb  = (tid & 15) * 4;

    float acc[8][4];
    #pragma unroll
    for (int i = 0; i < 8; i++)
        #pragma unroll
        for (int j = 0; j < 4; j++) acc[i][j] = 0.f;

    {
        float4 va0 = *(const float4*)(Ab + (size_t)r0*LDH1 + c40);
        float4 va1 = *(const float4*)(Ab + (size_t)r1*LDH1 + c41);
        float4 vb  = *(const float4*)(Bb + (size_t)rb*Ddim + cb);
        As[0][c40+0][r0] = va0.x; As[0][c40+1][r0] = va0.y;
        As[0][c40+2][r0] = va0.z; As[0][c40+3][r0] = va0.w;
        As[0][c41+0][r1] = va1.x; As[0][c41+1][r1] = va1.y;
        As[0][c41+2][r1] = va1.z; As[0][c41+3][r1] = va1.w;
        *(float4*)&Bs[0][rb][cb] = vb;
    }
    __syncthreads();

    const int nstage = HF / 16;   // 24
    for (int s = 0; s < nstage; s++) {
        int cur = s & 1, nxt = cur ^ 1;
        float4 pa0, pa1, pb;
        bool has_next = (s + 1 < nstage);
        if (has_next) {
            int kn = (s + 1) * 16;
            pa0 = *(const float4*)(Ab + (size_t)r0*LDH1 + kn + c40);
            pa1 = *(const float4*)(Ab + (size_t)r1*LDH1 + kn + c41);
            pb  = *(const float4*)(Bb + (size_t)(kn + rb)*Ddim + cb);
        }
        #pragma unroll
        for (int k = 0; k < 16; k++) {
            float4 a0 = *(const float4*)&As[cur][k][ty*8];
            float4 a1 = *(const float4*)&As[cur][k][ty*8+4];
            float4 b0 = *(const float4*)&Bs[cur][k][tx*4];
            float a[8] = {a0.x,a0.y,a0.z,a0.w,a1.x,a1.y,a1.z,a1.w};
            float bb[4] = {b0.x,b0.y,b0.z,b0.w};
            #pragma unroll
            for (int i = 0; i < 8; i++)
                #pragma unroll
                for (int j = 0; j < 4; j++) acc[i][j] += a[i]*bb[j];
        }
        if (has_next) {
            As[nxt][c40+0][r0] = pa0.x; As[nxt][c40+1][r0] = pa0.y;
            As[nxt][c40+2][r0] = pa0.z; As[nxt][c40+3][r0] = pa0.w;
            As[nxt][c41+0][r1] = pa1.x; As[nxt][c41+1][r1] = pa1.y;
            As[nxt][c41+2][r1] = pa1.z; As[nxt][c41+3][r1] = pa1.w;
            *(float4*)&Bs[nxt][rb][cb] = pb;
        }
        __syncthreads();
    }

    #pragma unroll
    for (int i = 0; i < 8; i++) {
        int row = by*128 + ty*8 + i;
        float* cp = g_h2all + (size_t)row*LDH2 + z*Ddim + bx*64 + tx*4;
        cp[0] = acc[i][0]; cp[1] = acc[i][1];
        cp[2] = acc[i][2]; cp[3] = acc[i][3];
    }
}

// batched es/ed projections for all 4 experts (float4 inner loop)
__global__ void k_esed4(const float* __restrict__ ma1s, const float* __restrict__ ma1d,
                        const float* __restrict__ da1s, const float* __restrict__ da1d) {
    int idx = blockIdx.x*blockDim.x + threadIdx.x;
    if (idx >= 4*ESN) return;
    int e = idx / ESN;
    int r = idx - e*ESN;
    int s  = r & (Sdim-1);
    int bh = r >> 10;
    int hh = bh % Hn;
    int b  = bh / Hn;
    const float4* hp = (const float4*)(g_hall + (size_t)(b*Sdim + s)*LDH + e*HF + hh*Hd);
    const float4* as = (const float4*)((((e == 0) ? ma1s : da1s + (e-1)*Hn*Hd)) + hh*Hd);
    const float4* ad = (const float4*)((((e == 0) ? ma1d : da1d + (e-1)*Hn*Hd)) + hh*Hd);
    float x = 0.f, y = 0.f;
    #pragma unroll
    for (int o = 0; o < Hd/4; o++) {
        float4 v = hp[o], a = as[o], d = ad[o];
        x += v.x*a.x + v.y*a.y + v.z*a.z + v.w*a.w;
        y += v.x*d.x + v.y*d.y + v.z*d.z + v.w*d.w;
    }
    g_es[idx] = x; g_ed[idx] = y;
}

// generic per-batch column mean: out[b*cols + c] = mean_r X[(b*Sdim + r)*ldx + c]
__global__ void k_colmean(const float* __restrict__ X, int ldx, int cols, float* __restrict__ out) {
    int idx = blockIdx.x*blockDim.x + threadIdx.x;
    if (idx >= Bdim*cols) return;
    int b = idx / cols, cc = idx - b*cols;
    const float* p = X + (size_t)b*Sdim*ldx + cc;
    float a0 = 0.f, a1 = 0.f, a2 = 0.f, a3 = 0.f;
    for (int r = 0; r < Sdim; r += 4) {
        a0 += p[(size_t)r*ldx];
        a1 += p[(size_t)(r+1)*ldx];
        a2 += p[(size_t)(r+2)*ldx];
        a3 += p[(size_t)(r+3)*ldx];
    }
    out[idx] = (a0 + a1 + a2 + a3) * (1.f/(float)Sdim);
}

// layer-1 sparse attention + ELU, batched: blockIdx.y = 0 main, 1..3 deputy.
// Aggregation: 4 neighbor-groups x 96 threads, float4 per thread, smem combine.
__global__ void __launch_bounds__(384) k_att1(void) {
    int row = blockIdx.x;
    int ee  = blockIdx.y;
    int b = row >> 10, s = row & 1023;
    __shared__ float sc[Hn][MAXDEG];
    __shared__ int   snbr[MAXDEG];
    __shared__ float sden[Hn];
    __shared__ __align__(16) float4 red4[4][96];
    const int* c = g_cnt + row*3;
    int lo = 0, hi;
    if      (ee == 0) hi = c[2];
    else if (ee == 1) hi = c[0];
    else if (ee == 2) { lo = c[0]; hi = c[1]; }
    else              { lo = c[1]; hi = c[2]; }
    int deg = hi - lo;
    int tid = threadIdx.x;
    if (deg == 0) {  // all scores -1e9 -> uniform attention over all S -> column mean
        for (int o = tid; o < HF; o += 384) {
            float v = g_meanh[b*LDH1 + ee*HF + o];
            g_h1all[(size_t)row*LDH1 + ee*HF + o] = (v > 0.f) ? v : expm1f(v);
        }
        return;
    }
    for (int j = tid; j < deg; j += 384) snbr[j] = g_nbr[row*MAXDEG + lo + j];
    __syncthreads();
    const float* esb = g_es + ee*ESN + b*Hn*Sdim;
    const float* edb = g_ed + ee*ESN + b*Hn*Sdim;
    for (int idx = tid; idx < Hn*deg; idx += 384) {
        int hh = idx / deg;
        int j  = idx - hh*deg;
        float v = esb[hh*Sdim + s] + edb[hh*Sdim + snbr[j]];
        sc[hh][j] = (v > 0.f) ? v : 0.2f*v;
    }
    __syncthreads();
    int warp = tid >> 5, lane = tid & 31;
    if (warp < Hn) {
        float m = -1e30f;
        for (int j = lane; j < deg; j += 32) m = fmaxf(m, sc[warp][j]);
        for (int o = 16; o; o >>= 1) m = fmaxf(m, __shfl_xor_sync(0xffffffffu, m, o));
        float su = 0.f;
        for (int j = lane; j < deg; j += 32) { float e = expf(sc[warp][j] - m); sc[warp][j] = e; su += e; }
        for (int o = 16; o; o >>= 1) su += __shfl_xor_sync(0xffffffffu, su, o);
        if (lane == 0) sden[warp] = su;
    }
    __syncthreads();
    // aggregation: group g over neighbors j == g (mod 4), float4 over 4 cols
    int g  = tid / 96;           // 0..3
    int cq = tid - g*96;         // 0..95
    int cid = cq * 4;            // column within expert block (same head for all 4)
    int hh = cid >> 6;
    const float* hb = g_hall + (size_t)(b*Sdim)*LDH + ee*HF + cid;
    float4 acc = make_float4(0.f, 0.f, 0.f, 0.f);
    #pragma unroll 2
    for (int j = g; j < deg; j += 4) {
        float w = sc[hh][j];
        float4 v = *(const float4*)(hb + (size_t)snbr[j]*LDH);
        acc.x += w*v.x; acc.y += w*v.y; acc.z += w*v.z; acc.w += w*v.w;
    }
    red4[g][cq] = acc;
    __syncthreads();
    if (tid < 96) {
        float4 a0 = red4[0][tid], a1 = red4[1][tid], a2 = red4[2][tid], a3 = red4[3][tid];
        int c0 = tid*4;
        float den = sden[c0 >> 6];
        float4 r;
        r.x = (a0.x + a1.x + a2.x + a3.x) / den;
        r.y = (a0.y + a1.y + a2.y + a3.y) / den;
        r.z = (a0.z + a1.z + a2.z + a3.z) / den;
        r.w = (a0.w + a1.w + a2.w + a3.w) / den;
        r.x = (r.x > 0.f) ? r.x : expm1f(r.x);
        r.y = (r.y > 0.f) ? r.y : expm1f(r.y);
        r.z = (r.z > 0.f) ? r.z : expm1f(r.z);
        r.w = (r.w > 0.f) ? r.w : expm1f(r.w);
        *(float4*)(g_h1all + (size_t)row*LDH1 + ee*HF + c0) = r;
    }
}

// batched layer-2 attention projections (float4 inner loop)
__global__ void k_s2d24(const float* __restrict__ ma2s, const float* __restrict__ ma2d,
                        const float* __restrict__ da2s, const float* __restrict__ da2d) {
    int idx = blockIdx.x*blockDim.x + threadIdx.x;
    if (idx >= 4*BS) return;
    int e   = idx / BS;
    int row = idx - e*BS;
    const float4* p  = (const float4*)(g_h2all + (size_t)row*LDH2 + e*Ddim);
    const float4* as = (const float4*)((e == 0) ? ma2s : da2s + (e-1)*Ddim);
    const float4* ad = (const float4*)((e == 0) ? ma2d : da2d + (e-1)*Ddim);
    float x = 0.f, y = 0.f;
    #pragma unroll 4
    for (int d = 0; d < Ddim/4; d++) {
        float4 v = p[d], a = as[d], dd = ad[d];
        x += v.x*a.x + v.y*a.y + v.z*a.z + v.w*a.w;
        y += v.x*dd.x + v.y*dd.y + v.z*dd.z + v.w*dd.w;
    }
    g_s2[idx] = x; g_d2[idx] = y;
}

// layer-2 sparse attention, batched: y=0 main -> g_main; y=1..3 -> g_dep3[e]
// Aggregation: 4 neighbor-groups x 64 threads, float4 per thread, smem combine.
__global__ void __launch_bounds__(256) k_att2(void) {
    int row = blockIdx.x;
    int ee  = blockIdx.y;
    if (ee > 0 && g_mask[(ee-1)*BS + row] == 0.f) return;  // output masked anyway
    int b = row >> 10;
    __shared__ float sc[MAXDEG];
    __shared__ int   snbr[MAXDEG];
    __shared__ float sden;
    __shared__ __align__(16) float4 red4[4][64];
    const int* c = g_cnt + row*3;
    int lo = 0, hi;
    if      (ee == 0) hi = c[2];
    else if (ee == 1) hi = c[0];
    else if (ee == 2) { lo = c[0]; hi = c[1]; }
    else              { lo = c[1]; hi = c[2]; }
    int deg = hi - lo;
    int tid = threadIdx.x;
    float* outp = (ee == 0) ? (g_main + (size_t)row*Ddim)
                            : (g_dep3 + (size_t)(ee-1)*BSD + (size_t)row*Ddim);
    if (deg == 0) {
        for (int o = tid; o < Ddim; o += 256)
            outp[o] = g_meanh2[b*LDH2 + ee*Ddim + o];
        return;
    }
    for (int j = tid; j < deg; j += 256) snbr[j] = g_nbr[row*MAXDEG + lo + j];
    __syncthreads();
    float srcsc = g_s2[ee*BS + row];
    const float* d2b = g_d2 + ee*BS + b*Sdim;
    for (int j = tid; j < deg; j += 256) {
        float v = srcsc + d2b[snbr[j]];
        sc[j] = (v > 0.f) ? v : 0.2f*v;
    }
    __syncthreads();
    if (tid < 32) {
        float m = -1e30f;
        for (int j = tid; j < deg; j += 32) m = fmaxf(m, sc[j]);
        for (int o = 16; o; o >>= 1) m = fmaxf(m, __shfl_xor_sync(0xffffffffu, m, o));
        float su = 0.f;
        for (int j = tid; j < deg; j += 32) { float e = expf(sc[j] - m); sc[j] = e; su += e; }
        for (int o = 16; o; o >>= 1) su += __shfl_xor_sync(0xffffffffu, su, o);
        if (tid == 0) sden = su;
    }
    __syncthreads();
    int g  = tid >> 6;           // 0..3
    int cq = tid & 63;           // 0..63
    int cid = cq * 4;
    const float* hb = g_h2all + (size_t)(b*Sdim)*LDH2 + ee*Ddim + cid;
    float4 acc = make_float4(0.f, 0.f, 0.f, 0.f);
    #pragma unroll 2
    for (int j = g; j < deg; j += 4) {
        float w = sc[j];
        float4 v = *(const float4*)(hb + (size_t)snbr[j]*LDH2);
        acc.x += w*v.x; acc.y += w*v.y; acc.z += w*v.z; acc.w += w*v.w;
    }
    red4[g][cq] = acc;
    __syncthreads();
    if (tid < 64) {
        float4 a0 = red4[0][tid], a1 = red4[1][tid], a2 = red4[2][tid], a3 = red4[3][tid];
        float den = sden;
        float4 r;
        r.x = (a0.x + a1.x + a2.x + a3.x) / den;
        r.y = (a0.y + a1.y + a2.y + a3.y) / den;
        r.z = (a0.z + a1.z + a2.z + a3.z) / den;
        r.w = (a0.w + a1.w + a2.w + a3.w) / den;
        *(float4*)(outp + tid*4) = r;
    }
}

// blend + final output + deterministic partial sums of blend weights
__global__ void __launch_bounds__(256) k_final(const float* __restrict__ bbias, float* __restrict__ out) {
    __shared__ float red[256];
    int t = threadIdx.x;
    int base = blockIdx.x*1024;
    float s = 0.f;
    #pragma unroll
    for (int l = 0; l < 4; l++) {
        int i   = base + l*256 + t;
        int row = i >> 8;
        int d   = i & (Ddim-1);
        float blendv = g_hall[(size_t)row*LDH + 4*HF + d];
        float w = 1.f / (1.f + expf(-(blendv + bbias[d])));
        float dep = g_mask[0*BS + row] * g_dep3[0*BSD + i]
                  + g_mask[1*BS + row] * g_dep3[1*BSD + i]
                  + g_mask[2*BS + row] * g_dep3[2*BSD + i];
        out[i] = w*g_main[i] + (1.f - w)*dep;
        s += w;
    }
    red[t] = s; __syncthreads();
    for (int o = 128; o; o >>= 1) { if (t < o) red[t] += red[t+o]; __syncthreads(); }
    if (t == 0) g_part[blockIdx.x] = red[0];
}

__global__ void k_scalar(float* __restrict__ out) {
    __shared__ float red[256];
    int t = threadIdx.x;
    float s = 0.f;
    for (int i = t; i < 1024; i += 256) s += g_part[i];
    red[t] = s; __syncthreads();
    for (int o = 128; o; o >>= 1) { if (t < o) red[t] += red[t+o]; __syncthreads(); }
    if (t == 0) {
        float mc = red[0] / (float)BSD;
        out[BSD]     = fabsf(mc - 0.6f) * 0.01f;
        out[BSD + 1] = mc;
    }
}

// ----------------------------- host launcher -----------------------------
extern "C" void kernel_launch(void* const* d_in, const int* in_sizes, int n_in,
                              void* d_out, int out_size) {
    const float* feature = (const float*)d_in[0];
    const float* adj     = (const float*)d_in[1];
    const float* mW1     = (const float*)d_in[2];
    const float* ma1s    = (const float*)d_in[3];
    const float* ma1d    = (const float*)d_in[4];
    const float* mW2     = (const float*)d_in[5];
    const float* ma2s    = (const float*)d_in[6];
    const float* ma2d    = (const float*)d_in[7];
    const float* dW1     = (const float*)d_in[8];
    const float* da1s    = (const float*)d_in[9];
    const float* da1d    = (const float*)d_in[10];
    const float* dW2     = (const float*)d_in[11];
    const float* da2s    = (const float*)d_in[12];
    const float* da2d    = (const float*)d_in[13];
    const float* rW      = (const float*)d_in[14];
    const float* bW      = (const float*)d_in[15];
    const float* bbias   = (const float*)d_in[16];
    float* out = (float*)d_out;

    static float *p_hall = nullptr, *p_h2all, *p_meanh, *p_meanh2;
    if (!p_hall) {
        cudaGetSymbolAddress((void**)&p_hall,   g_hall);
        cudaGetSymbolAddress((void**)&p_h2all,  g_h2all);
        cudaGetSymbolAddress((void**)&p_meanh,  g_meanh);
        cudaGetSymbolAddress((void**)&p_meanh2, g_meanh2);
    }

    k_router   <<<512, 256>>>(feature, rW);
    k_build_csr<<<512, 256>>>(adj);
    k_pack     <<<(Ddim*NBIG + 255)/256, 256>>>(mW1, dW1, bW);

    // fused layer-1 (4 experts) + blend GEMM: 896 CTAs (128x64 tiles)
    k_gemm_big<<<dim3(NBIG/64, BS/128), 256>>>(feature);

    k_esed4  <<<(4*ESN + 255)/256, 256>>>(ma1s, ma1d, da1s, da1d);
    k_colmean<<<(Bdim*LDH1 + 255)/256, 256>>>(p_hall, LDH, LDH1, p_meanh);

    k_att1<<<dim3(BS, 4), 384>>>();

    // batched layer-2 GEMM over 4 experts: 512 CTAs (128x64 tiles)
    k_gemm2<<<dim3(Ddim/64, BS/128, 4), 256>>>(mW2, dW2);

    k_s2d24  <<<(4*BS + 255)/256, 256>>>(ma2s, ma2d, da2s, da2d);
    k_colmean<<<(Bdim*LDH2 + 255)/256, 256>>>(p_h2all, LDH2, LDH2, p_meanh2);

    k_att2<<<dim3(BS, 4), 256>>>();

    k_final<<<1024, 256>>>(bbias, out);
    if (out_size >= BSD + 2) k_scalar<<<1, 256>>>(out);
}

// round 13
// speedup vs baseline: 1.1920x; 1.0260x over previous
#include <cuda_runtime.h>
#include <math.h>

// Problem constants (fixed by setup_inputs)
#define Bdim 4
#define Sdim 1024
#define Ddim 256
#define Hn   6
#define Hd   64
#define HF   384          // Hn*Hd
#define En   3
#define SENT_END 988      // S - sect - doc
#define SECT_END 1020     // S - doc
#define MAXDEG 256
#define BS  (Bdim*Sdim)   // 4096
#define BSD (BS*Ddim)     // 1048576
#define NBIG 1792         // 4*HF + Ddim  (4 experts layer-1 + blend)
#define LDH  1792         // g_hall row stride
#define LDH1 1536         // g_h1all row stride (4*HF)
#define LDH2 1024         // g_h2all row stride (4*Ddim)
#define ESN  (Bdim*Hn*Sdim)  // 24576 per expert

// ----------------------------- device scratch -----------------------------
__device__ __align__(128) int   g_nbr[BS*MAXDEG];      // CSR neighbor lists (ascending j)
__device__ __align__(128) int   g_cnt[BS*3];           // cumulative counts: <988, <1020, total
__device__ __align__(128) float g_mask[En*BS];         // routing mask per deputy expert
__device__ __align__(128) float g_Bpack[Ddim*NBIG];    // packed B: [W1t m|d0|d1|d2 | bW]
__device__ __align__(128) float g_hall [BS*LDH];       // layer-1 out (4 experts) + blend logits
__device__ __align__(128) float g_h1all[BS*LDH1];      // att1+ELU out, 4 experts
__device__ __align__(128) float g_h2all[BS*LDH2];      // layer-2 out, 4 experts
__device__ __align__(128) float g_es[4*ESN];
__device__ __align__(128) float g_ed[4*ESN];
__device__ __align__(128) float g_s2[4*BS];
__device__ __align__(128) float g_d2[4*BS];
__device__ __align__(128) float g_main[BSD];
__device__ __align__(128) float g_dep3[En*BSD];        // per-deputy att2 outputs
__device__ __align__(128) float g_meanh [Bdim*LDH1];   // column means of g_hall (per b)
__device__ __align__(128) float g_meanh2[Bdim*LDH2];   // column means of g_h2all (per b)
__device__ __align__(128) float g_part[1024];

// ----------------------------- kernels -----------------------------

// one warp per row: compact adjacency row into CSR (preserves ascending j order)
__global__ void k_build_csr(const float* __restrict__ adj) {
    int warp = (blockIdx.x*blockDim.x + threadIdx.x) >> 5;
    int lane = threadIdx.x & 31;
    if (warp >= BS) return;
    const float* row = adj + (size_t)warp * Sdim;
    int cnt = 0, c0 = 0, c1 = 0;
    for (int c = 0; c < Sdim; c += 32) {
        int j = c + lane;
        float v = row[j];
        unsigned m = __ballot_sync(0xffffffffu, v > 0.f);
        if (v > 0.f) {
            int pos = cnt + __popc(m & ((1u << lane) - 1u));
            if (pos < MAXDEG) g_nbr[warp*MAXDEG + pos] = j;
        }
        unsigned msent = __ballot_sync(0xffffffffu, j < SENT_END);
        unsigned msect = __ballot_sync(0xffffffffu, j < SECT_END);
        cnt += __popc(m);
        c0  += __popc(m & msent);
        c1  += __popc(m & msect);
    }
    if (lane == 0) {
        g_cnt[warp*3+0] = c0; g_cnt[warp*3+1] = c1; g_cnt[warp*3+2] = cnt;
    }
}

// one warp per node: router logits; top-2 of 3 == exclude argmin (ties -> larger idx)
__global__ void k_router(const float* __restrict__ x, const float* __restrict__ rw) {
    int warp = (blockIdx.x*blockDim.x + threadIdx.x) >> 5;
    int lane = threadIdx.x & 31;
    if (warp >= BS) return;
    const float* xp = x + (size_t)warp * Ddim;
    float l0 = 0.f, l1 = 0.f, l2 = 0.f;
    for (int d = lane; d < Ddim; d += 32) {
        float v = xp[d];
        l0 += v * rw[d*3+0];
        l1 += v * rw[d*3+1];
        l2 += v * rw[d*3+2];
    }
    for (int o = 16; o; o >>= 1) {
        l0 += __shfl_xor_sync(0xffffffffu, l0, o);
        l1 += __shfl_xor_sync(0xffffffffu, l1, o);
        l2 += __shfl_xor_sync(0xffffffffu, l2, o);
    }
    if (lane == 0) {
        int excl = 0; float mn = l0;
        if (l1 <= mn) { mn = l1; excl = 1; }
        if (l2 <= mn) { mn = l2; excl = 2; }
        g_mask[0*BS + warp] = (excl == 0) ? 0.f : 1.f;
        g_mask[1*BS + warp] = (excl == 1) ? 0.f : 1.f;
        g_mask[2*BS + warp] = (excl == 2) ? 0.f : 1.f;
    }
}

// build packed B [D=256 rows][NBIG=1792 cols]:
// cols [e*384 + hh*64 + o] = W1[e][hh][f][o] transposed; cols [1536+d] = bW[f][d]
__global__ void k_pack(const float* __restrict__ mW1, const float* __restrict__ dW1,
                       const float* __restrict__ bW) {
    int i = blockIdx.x*blockDim.x + threadIdx.x;
    if (i >= Ddim*NBIG) return;
    int f   = i / NBIG;
    int col = i - f*NBIG;
    float v;
    if (col < 4*HF) {
        int e  = col / HF;
        int ho = col - e*HF;
        int hh = ho >> 6, o = ho & 63;
        const float* src = (e == 0) ? mW1 : (dW1 + (size_t)(e-1)*Hn*Ddim*Hd);
        v = src[(hh*Ddim + f)*Hd + o];
    } else {
        v = bW[f*Ddim + (col - 4*HF)];
    }
    g_Bpack[i] = v;
}

// ---------------------------------------------------------------------------
// Fused big SGEMM: g_hall[4096,1792] = feature[4096,256] @ g_Bpack[256,1792]
// Tile 128x128, 256 threads, 8Mx8N micro-tile, double-buffered smem with
// register prefetch (one sync per k-step). FMA:LDS = 2:1 per k-step.
// Column tiles: bx 0-2 main, 3-5 dep0, 6-8 dep1, 9-11 dep2, 12-13 blend.
// ---------------------------------------------------------------------------
__global__ void __launch_bounds__(256, 2) k_gemm_big(const float* __restrict__ A) {
    __shared__ __align__(16) float As[2][16][128];
    __shared__ __align__(16) float Bs[2][16][128];
    int tid = threadIdx.x;
    int tx = tid & 15;   // N micro (x8)
    int ty = tid >> 4;   // M micro (x8)
    int bx = blockIdx.x; // N tile (0..13)
    int by = blockIdx.y; // M tile (0..31)
    const float* rowmask = nullptr;
    int seg = bx / 3;    // 384 = 3*128 column block per expert
    if (bx < 12 && seg > 0) rowmask = g_mask + (size_t)(seg-1)*BS;

    const float* Ab = A + (size_t)by*128*Ddim;
    const float* Bb = g_Bpack + bx*128;

    int ra0 = tid >> 2,         ca0 = (tid & 3) * 4;
    int ra1 = (tid + 256) >> 2, ca1 = ((tid + 256) & 3) * 4;
    int rb0 = tid >> 5,         cb0 = (tid & 31) * 4;
    int rb1 = (tid + 256) >> 5, cb1 = ((tid + 256) & 31) * 4;

    float acc[8][8];
    #pragma unroll
    for (int i = 0; i < 8; i++)
        #pragma unroll
        for (int j = 0; j < 8; j++) acc[i][j] = 0.f;

    {   // stage 0
        float4 va0 = *(const float4*)(Ab + (size_t)ra0*Ddim + ca0);
        float4 va1 = *(const float4*)(Ab + (size_t)ra1*Ddim + ca1);
        float4 vb0 = *(const float4*)(Bb + (size_t)rb0*NBIG + cb0);
        float4 vb1 = *(const float4*)(Bb + (size_t)rb1*NBIG + cb1);
        As[0][ca0+0][ra0] = va0.x; As[0][ca0+1][ra0] = va0.y;
        As[0][ca0+2][ra0] = va0.z; As[0][ca0+3][ra0] = va0.w;
        As[0][ca1+0][ra1] = va1.x; As[0][ca1+1][ra1] = va1.y;
        As[0][ca1+2][ra1] = va1.z; As[0][ca1+3][ra1] = va1.w;
        *(float4*)&Bs[0][rb0][cb0] = vb0;
        *(float4*)&Bs[0][rb1][cb1] = vb1;
    }
    __syncthreads();

    const int nstage = Ddim / 16;   // 16
    for (int s = 0; s < nstage; s++) {
        int cur = s & 1, nxt = cur ^ 1;
        float4 pa0, pa1, pb0, pb1;
        bool has_next = (s + 1 < nstage);
        if (has_next) {
            int kn = (s + 1) * 16;
            pa0 = *(const float4*)(Ab + (size_t)ra0*Ddim + kn + ca0);
            pa1 = *(const float4*)(Ab + (size_t)ra1*Ddim + kn + ca1);
            pb0 = *(const float4*)(Bb + (size_t)(kn + rb0)*NBIG + cb0);
            pb1 = *(const float4*)(Bb + (size_t)(kn + rb1)*NBIG + cb1);
        }
        #pragma unroll
        for (int k = 0; k < 16; k++) {
            float4 a0 = *(const float4*)&As[cur][k][ty*8];
            float4 a1 = *(const float4*)&As[cur][k][ty*8+4];
            float4 b0 = *(const float4*)&Bs[cur][k][tx*8];
            float4 b1 = *(const float4*)&Bs[cur][k][tx*8+4];
            float a[8] = {a0.x,a0.y,a0.z,a0.w,a1.x,a1.y,a1.z,a1.w};
            float b[8] = {b0.x,b0.y,b0.z,b0.w,b1.x,b1.y,b1.z,b1.w};
            #pragma unroll
            for (int i = 0; i < 8; i++)
                #pragma unroll
                for (int j = 0; j < 8; j++) acc[i][j] += a[i]*b[j];
        }
        if (has_next) {
            As[nxt][ca0+0][ra0] = pa0.x; As[nxt][ca0+1][ra0] = pa0.y;
            As[nxt][ca0+2][ra0] = pa0.z; As[nxt][ca0+3][ra0] = pa0.w;
            As[nxt][ca1+0][ra1] = pa1.x; As[nxt][ca1+1][ra1] = pa1.y;
            As[nxt][ca1+2][ra1] = pa1.z; As[nxt][ca1+3][ra1] = pa1.w;
            *(float4*)&Bs[nxt][rb0][cb0] = pb0;
            *(float4*)&Bs[nxt][rb1][cb1] = pb1;
        }
        __syncthreads();
    }

    #pragma unroll
    for (int i = 0; i < 8; i++) {
        int row = by*128 + ty*8 + i;
        float mv = rowmask ? rowmask[row] : 1.f;
        float* cp = g_hall + (size_t)row*LDH + bx*128 + tx*8;
        *(float4*)(cp)     = make_float4(acc[i][0]*mv, acc[i][1]*mv, acc[i][2]*mv, acc[i][3]*mv);
        *(float4*)(cp + 4) = make_float4(acc[i][4]*mv, acc[i][5]*mv, acc[i][6]*mv, acc[i][7]*mv);
    }
}

// ---------------------------------------------------------------------------
// Batched layer-2 SGEMM over blockIdx.z = expert (0=main, 1..3 deputies):
// g_h2all[:, z*256:(z+1)*256] = g_h1all[:, z*384:(z+1)*384] @ W2_z[384,256]
// Same pipelined 128x128 / 8x8 tile.
// ---------------------------------------------------------------------------
__global__ void __launch_bounds__(256, 2) k_gemm2(const float* __restrict__ mW2,
                                                  const float* __restrict__ dW2) {
    __shared__ __align__(16) float As[2][16][128];
    __shared__ __align__(16) float Bs[2][16][128];
    int tid = threadIdx.x;
    int tx = tid & 15;
    int ty = tid >> 4;
    int bx = blockIdx.x;  // 0..1 (N=256)
    int by = blockIdx.y;  // 0..31
    int z  = blockIdx.z;  // expert
    const float* Ap = g_h1all + (size_t)z*HF;                          // lda = LDH1
    const float* Bp = (z == 0) ? mW2 : (dW2 + (size_t)(z-1)*HF*Ddim);  // ldb = 256
    const float* Ab = Ap + (size_t)by*128*LDH1;
    const float* Bb = Bp + bx*128;

    int ra0 = tid >> 2,         ca0 = (tid & 3) * 4;
    int ra1 = (tid + 256) >> 2, ca1 = ((tid + 256) & 3) * 4;
    int rb0 = tid >> 5,         cb0 = (tid & 31) * 4;
    int rb1 = (tid + 256) >> 5, cb1 = ((tid + 256) & 31) * 4;

    float acc[8][8];
    #pragma unroll
    for (int i = 0; i < 8; i++)
        #pragma unroll
        for (int j = 0; j < 8; j++) acc[i][j] = 0.f;

    {
        float4 va0 = *(const float4*)(Ab + (size_t)ra0*LDH1 + ca0);
        float4 va1 = *(const float4*)(Ab + (size_t)ra1*LDH1 + ca1);
        float4 vb0 = *(const float4*)(Bb + (size_t)rb0*Ddim + cb0);
        float4 vb1 = *(const float4*)(Bb + (size_t)rb1*Ddim + cb1);
        As[0][ca0+0][ra0] = va0.x; As[0][ca0+1][ra0] = va0.y;
        As[0][ca0+2][ra0] = va0.z; As[0][ca0+3][ra0] = va0.w;
        As[0][ca1+0][ra1] = va1.x; As[0][ca1+1][ra1] = va1.y;
        As[0][ca1+2][ra1] = va1.z; As[0][ca1+3][ra1] = va1.w;
        *(float4*)&Bs[0][rb0][cb0] = vb0;
        *(float4*)&Bs[0][rb1][cb1] = vb1;
    }
    __syncthreads();

    const int nstage = HF / 16;   // 24
    for (int s = 0; s < nstage; s++) {
        int cur = s & 1, nxt = cur ^ 1;
        float4 pa0, pa1, pb0, pb1;
        bool has_next = (s + 1 < nstage);
        if (has_next) {
            int kn = (s + 1) * 16;
            pa0 = *(const float4*)(Ab + (size_t)ra0*LDH1 + kn + ca0);
            pa1 = *(const float4*)(Ab + (size_t)ra1*LDH1 + kn + ca1);
            pb0 = *(const float4*)(Bb + (size_t)(kn + rb0)*Ddim + cb0);
            pb1 = *(const float4*)(Bb + (size_t)(kn + rb1)*Ddim + cb1);
        }
        #pragma unroll
        for (int k = 0; k < 16; k++) {
            float4 a0 = *(const float4*)&As[cur][k][ty*8];
            float4 a1 = *(const float4*)&As[cur][k][ty*8+4];
            float4 b0 = *(const float4*)&Bs[cur][k][tx*8];
            float4 b1 = *(const float4*)&Bs[cur][k][tx*8+4];
            float a[8] = {a0.x,a0.y,a0.z,a0.w,a1.x,a1.y,a1.z,a1.w};
            float b[8] = {b0.x,b0.y,b0.z,b0.w,b1.x,b1.y,b1.z,b1.w};
            #pragma unroll
            for (int i = 0; i < 8; i++)
                #pragma unroll
                for (int j = 0; j < 8; j++) acc[i][j] += a[i]*b[j];
        }
        if (has_next) {
            As[nxt][ca0+0][ra0] = pa0.x; As[nxt][ca0+1][ra0] = pa0.y;
            As[nxt][ca0+2][ra0] = pa0.z; As[nxt][ca0+3][ra0] = pa0.w;
            As[nxt][ca1+0][ra1] = pa1.x; As[nxt][ca1+1][ra1] = pa1.y;
            As[nxt][ca1+2][ra1] = pa1.z; As[nxt][ca1+3][ra1] = pa1.w;
            *(float4*)&Bs[nxt][rb0][cb0] = pb0;
            *(float4*)&Bs[nxt][rb1][cb1] = pb1;
        }
        __syncthreads();
    }

    #pragma unroll
    for (int i = 0; i < 8; i++) {
        int row = by*128 + ty*8 + i;
        float* cp = g_h2all + (size_t)row*LDH2 + z*Ddim + bx*128 + tx*8;
        *(float4*)(cp)     = make_float4(acc[i][0], acc[i][1], acc[i][2], acc[i][3]);
        *(float4*)(cp + 4) = make_float4(acc[i][4], acc[i][5], acc[i][6], acc[i][7]);
    }
}

// batched es/ed projections for all 4 experts (float4 inner loop)
__global__ void k_esed4(const float* __restrict__ ma1s, const float* __restrict__ ma1d,
                        const float* __restrict__ da1s, const float* __restrict__ da1d) {
    int idx = blockIdx.x*blockDim.x + threadIdx.x;
    if (idx >= 4*ESN) return;
    int e = idx / ESN;
    int r = idx - e*ESN;
    int s  = r & (Sdim-1);
    int bh = r >> 10;
    int hh = bh % Hn;
    int b  = bh / Hn;
    const float4* hp = (const float4*)(g_hall + (size_t)(b*Sdim + s)*LDH + e*HF + hh*Hd);
    const float4* as = (const float4*)((((e == 0) ? ma1s : da1s + (e-1)*Hn*Hd)) + hh*Hd);
    const float4* ad = (const float4*)((((e == 0) ? ma1d : da1d + (e-1)*Hn*Hd)) + hh*Hd);
    float x = 0.f, y = 0.f;
    #pragma unroll
    for (int o = 0; o < Hd/4; o++) {
        float4 v = hp[o], a = as[o], d = ad[o];
        x += v.x*a.x + v.y*a.y + v.z*a.z + v.w*a.w;
        y += v.x*d.x + v.y*d.y + v.z*d.z + v.w*d.w;
    }
    g_es[idx] = x; g_ed[idx] = y;
}

// generic per-batch column mean: out[b*cols + c] = mean_r X[(b*Sdim + r)*ldx + c]
__global__ void k_colmean(const float* __restrict__ X, int ldx, int cols, float* __restrict__ out) {
    int idx = blockIdx.x*blockDim.x + threadIdx.x;
    if (idx >= Bdim*cols) return;
    int b = idx / cols, cc = idx - b*cols;
    const float* p = X + (size_t)b*Sdim*ldx + cc;
    float a0 = 0.f, a1 = 0.f, a2 = 0.f, a3 = 0.f;
    for (int r = 0; r < Sdim; r += 4) {
        a0 += p[(size_t)r*ldx];
        a1 += p[(size_t)(r+1)*ldx];
        a2 += p[(size_t)(r+2)*ldx];
        a3 += p[(size_t)(r+3)*ldx];
    }
    out[idx] = (a0 + a1 + a2 + a3) * (1.f/(float)Sdim);
}

// layer-1 sparse attention + ELU, batched: blockIdx.y = 0 main, 1..3 deputy.
// Aggregation: 4 neighbor-groups x 96 threads, float4 per thread, smem combine.
__global__ void __launch_bounds__(384) k_att1(void) {
    int row = blockIdx.x;
    int ee  = blockIdx.y;
    int b = row >> 10, s = row & 1023;
    __shared__ float sc[Hn][MAXDEG];
    __shared__ int   snbr[MAXDEG];
    __shared__ float sden[Hn];
    __shared__ __align__(16) float4 red4[4][96];
    const int* c = g_cnt + row*3;
    int lo = 0, hi;
    if      (ee == 0) hi = c[2];
    else if (ee == 1) hi = c[0];
    else if (ee == 2) { lo = c[0]; hi = c[1]; }
    else              { lo = c[1]; hi = c[2]; }
    int deg = hi - lo;
    int tid = threadIdx.x;
    if (deg == 0) {  // all scores -1e9 -> uniform attention over all S -> column mean
        for (int o = tid; o < HF; o += 384) {
            float v = g_meanh[b*LDH1 + ee*HF + o];
            g_h1all[(size_t)row*LDH1 + ee*HF + o] = (v > 0.f) ? v : expm1f(v);
        }
        return;
    }
    for (int j = tid; j < deg; j += 384) snbr[j] = g_nbr[row*MAXDEG + lo + j];
    __syncthreads();
    const float* esb = g_es + ee*ESN + b*Hn*Sdim;
    const float* edb = g_ed + ee*ESN + b*Hn*Sdim;
    for (int idx = tid; idx < Hn*deg; idx += 384) {
        int hh = idx / deg;
        int j  = idx - hh*deg;
        float v = esb[hh*Sdim + s] + edb[hh*Sdim + snbr[j]];
        sc[hh][j] = (v > 0.f) ? v : 0.2f*v;
    }
    __syncthreads();
    int warp = tid >> 5, lane = tid & 31;
    if (warp < Hn) {
        float m = -1e30f;
        for (int j = lane; j < deg; j += 32) m = fmaxf(m, sc[warp][j]);
        for (int o = 16; o; o >>= 1) m = fmaxf(m, __shfl_xor_sync(0xffffffffu, m, o));
        float su = 0.f;
        for (int j = lane; j < deg; j += 32) { float e = expf(sc[warp][j] - m); sc[warp][j] = e; su += e; }
        for (int o = 16; o; o >>= 1) su += __shfl_xor_sync(0xffffffffu, su, o);
        if (lane == 0) sden[warp] = su;
    }
    __syncthreads();
    // aggregation: group g over neighbors j == g (mod 4), float4 over 4 cols
    int g  = tid / 96;           // 0..3
    int cq = tid - g*96;         // 0..95
    int cid = cq * 4;            // column within expert block (same head for all 4)
    int hh = cid >> 6;
    const float* hb = g_hall + (size_t)(b*Sdim)*LDH + ee*HF + cid;
    float4 acc = make_float4(0.f, 0.f, 0.f, 0.f);
    #pragma unroll 2
    for (int j = g; j < deg; j += 4) {
        float w = sc[hh][j];
        float4 v = *(const float4*)(hb + (size_t)snbr[j]*LDH);
        acc.x += w*v.x; acc.y += w*v.y; acc.z += w*v.z; acc.w += w*v.w;
    }
    red4[g][cq] = acc;
    __syncthreads();
    if (tid < 96) {
        float4 a0 = red4[0][tid], a1 = red4[1][tid], a2 = red4[2][tid], a3 = red4[3][tid];
        int c0 = tid*4;
        float den = sden[c0 >> 6];
        float4 r;
        r.x = (a0.x + a1.x + a2.x + a3.x) / den;
        r.y = (a0.y + a1.y + a2.y + a3.y) / den;
        r.z = (a0.z + a1.z + a2.z + a3.z) / den;
        r.w = (a0.w + a1.w + a2.w + a3.w) / den;
        r.x = (r.x > 0.f) ? r.x : expm1f(r.x);
        r.y = (r.y > 0.f) ? r.y : expm1f(r.y);
        r.z = (r.z > 0.f) ? r.z : expm1f(r.z);
        r.w = (r.w > 0.f) ? r.w : expm1f(r.w);
        *(float4*)(g_h1all + (size_t)row*LDH1 + ee*HF + c0) = r;
    }
}

// batched layer-2 attention projections (float4 inner loop)
__global__ void k_s2d24(const float* __restrict__ ma2s, const float* __restrict__ ma2d,
                        const float* __restrict__ da2s, const float* __restrict__ da2d) {
    int idx = blockIdx.x*blockDim.x + threadIdx.x;
    if (idx >= 4*BS) return;
    int e   = idx / BS;
    int row = idx - e*BS;
    const float4* p  = (const float4*)(g_h2all + (size_t)row*LDH2 + e*Ddim);
    const float4* as = (const float4*)((e == 0) ? ma2s : da2s + (e-1)*Ddim);
    const float4* ad = (const float4*)((e == 0) ? ma2d : da2d + (e-1)*Ddim);
    float x = 0.f, y = 0.f;
    #pragma unroll 4
    for (int d = 0; d < Ddim/4; d++) {
        float4 v = p[d], a = as[d], dd = ad[d];
        x += v.x*a.x + v.y*a.y + v.z*a.z + v.w*a.w;
        y += v.x*dd.x + v.y*dd.y + v.z*dd.z + v.w*dd.w;
    }
    g_s2[idx] = x; g_d2[idx] = y;
}

// layer-2 sparse attention, batched: y=0 main -> g_main; y=1..3 -> g_dep3[e]
// Aggregation: 4 neighbor-groups x 64 threads, float4 per thread, smem combine.
__global__ void __launch_bounds__(256) k_att2(void) {
    int row = blockIdx.x;
    int ee  = blockIdx.y;
    if (ee > 0 && g_mask[(ee-1)*BS + row] == 0.f) return;  // output masked anyway
    int b = row >> 10;
    __shared__ float sc[MAXDEG];
    __shared__ int   snbr[MAXDEG];
    __shared__ float sden;
    __shared__ __align__(16) float4 red4[4][64];
    const int* c = g_cnt + row*3;
    int lo = 0, hi;
    if      (ee == 0) hi = c[2];
    else if (ee == 1) hi = c[0];
    else if (ee == 2) { lo = c[0]; hi = c[1]; }
    else              { lo = c[1]; hi = c[2]; }
    int deg = hi - lo;
    int tid = threadIdx.x;
    float* outp = (ee == 0) ? (g_main + (size_t)row*Ddim)
                            : (g_dep3 + (size_t)(ee-1)*BSD + (size_t)row*Ddim);
    if (deg == 0) {
        for (int o = tid; o < Ddim; o += 256)
            outp[o] = g_meanh2[b*LDH2 + ee*Ddim + o];
        return;
    }
    for (int j = tid; j < deg; j += 256) snbr[j] = g_nbr[row*MAXDEG + lo + j];
    __syncthreads();
    float srcsc = g_s2[ee*BS + row];
    const float* d2b = g_d2 + ee*BS + b*Sdim;
    for (int j = tid; j < deg; j += 256) {
        float v = srcsc + d2b[snbr[j]];
        sc[j] = (v > 0.f) ? v : 0.2f*v;
    }
    __syncthreads();
    if (tid < 32) {
        float m = -1e30f;
        for (int j = tid; j < deg; j += 32) m = fmaxf(m, sc[j]);
        for (int o = 16; o; o >>= 1) m = fmaxf(m, __shfl_xor_sync(0xffffffffu, m, o));
        float su = 0.f;
        for (int j = tid; j < deg; j += 32) { float e = expf(sc[j] - m); sc[j] = e; su += e; }
        for (int o = 16; o; o >>= 1) su += __shfl_xor_sync(0xffffffffu, su, o);
        if (tid == 0) sden = su;
    }
    __syncthreads();
    int g  = tid >> 6;           // 0..3
    int cq = tid & 63;           // 0..63
    int cid = cq * 4;
    const float* hb = g_h2all + (size_t)(b*Sdim)*LDH2 + ee*Ddim + cid;
    float4 acc = make_float4(0.f, 0.f, 0.f, 0.f);
    #pragma unroll 2
    for (int j = g; j < deg; j += 4) {
        float w = sc[j];
        float4 v = *(const float4*)(hb + (size_t)snbr[j]*LDH2);
        acc.x += w*v.x; acc.y += w*v.y; acc.z += w*v.z; acc.w += w*v.w;
    }
    red4[g][cq] = acc;
    __syncthreads();
    if (tid < 64) {
        float4 a0 = red4[0][tid], a1 = red4[1][tid], a2 = red4[2][tid], a3 = red4[3][tid];
        float den = sden;
        float4 r;
        r.x = (a0.x + a1.x + a2.x + a3.x) / den;
        r.y = (a0.y + a1.y + a2.y + a3.y) / den;
        r.z = (a0.z + a1.z + a2.z + a3.z) / den;
        r.w = (a0.w + a1.w + a2.w + a3.w) / den;
        *(float4*)(outp + tid*4) = r;
    }
}

// blend + final output + deterministic partial sums of blend weights
__global__ void __launch_bounds__(256) k_final(const float* __restrict__ bbias, float* __restrict__ out) {
    __shared__ float red[256];
    int t = threadIdx.x;
    int base = blockIdx.x*1024;
    float s = 0.f;
    #pragma unroll
    for (int l = 0; l < 4; l++) {
        int i   = base + l*256 + t;
        int row = i >> 8;
        int d   = i & (Ddim-1);
        float blendv = g_hall[(size_t)row*LDH + 4*HF + d];
        float w = 1.f / (1.f + expf(-(blendv + bbias[d])));
        float dep = g_mask[0*BS + row] * g_dep3[0*BSD + i]
                  + g_mask[1*BS + row] * g_dep3[1*BSD + i]
                  + g_mask[2*BS + row] * g_dep3[2*BSD + i];
        out[i] = w*g_main[i] + (1.f - w)*dep;
        s += w;
    }
    red[t] = s; __syncthreads();
    for (int o = 128; o; o >>= 1) { if (t < o) red[t] += red[t+o]; __syncthreads(); }
    if (t == 0) g_part[blockIdx.x] = red[0];
}

__global__ void k_scalar(float* __restrict__ out) {
    __shared__ float red[256];
    int t = threadIdx.x;
    float s = 0.f;
    for (int i = t; i < 1024; i += 256) s += g_part[i];
    red[t] = s; __syncthreads();
    for (int o = 128; o; o >>= 1) { if (t < o) red[t] += red[t+o]; __syncthreads(); }
    if (t == 0) {
        float mc = red[0] / (float)BSD;
        out[BSD]     = fabsf(mc - 0.6f) * 0.01f;
        out[BSD + 1] = mc;
    }
}

// ----------------------------- host launcher -----------------------------
extern "C" void kernel_launch(void* const* d_in, const int* in_sizes, int n_in,
                              void* d_out, int out_size) {
    const float* feature = (const float*)d_in[0];
    const float* adj     = (const float*)d_in[1];
    const float* mW1     = (const float*)d_in[2];
    const float* ma1s    = (const float*)d_in[3];
    const float* ma1d    = (const float*)d_in[4];
    const float* mW2     = (const float*)d_in[5];
    const float* ma2s    = (const float*)d_in[6];
    const float* ma2d    = (const float*)d_in[7];
    const float* dW1     = (const float*)d_in[8];
    const float* da1s    = (const float*)d_in[9];
    const float* da1d    = (const float*)d_in[10];
    const float* dW2     = (const float*)d_in[11];
    const float* da2s    = (const float*)d_in[12];
    const float* da2d    = (const float*)d_in[13];
    const float* rW      = (const float*)d_in[14];
    const float* bW      = (const float*)d_in[15];
    const float* bbias   = (const float*)d_in[16];
    float* out = (float*)d_out;

    static float *p_hall = nullptr, *p_h2all, *p_meanh, *p_meanh2;
    if (!p_hall) {
        cudaGetSymbolAddress((void**)&p_hall,   g_hall);
        cudaGetSymbolAddress((void**)&p_h2all,  g_h2all);
        cudaGetSymbolAddress((void**)&p_meanh,  g_meanh);
        cudaGetSymbolAddress((void**)&p_meanh2, g_meanh2);
    }

    k_router   <<<512, 256>>>(feature, rW);
    k_build_csr<<<512, 256>>>(adj);
    k_pack     <<<(Ddim*NBIG + 255)/256, 256>>>(mW1, dW1, bW);

    // fused layer-1 (4 experts) + blend GEMM: 448 CTAs (128x128 tiles)
    k_gemm_big<<<dim3(NBIG/128, BS/128), 256>>>(feature);

    k_esed4  <<<(4*ESN + 255)/256, 256>>>(ma1s, ma1d, da1s, da1d);
    k_colmean<<<(Bdim*LDH1 + 255)/256, 256>>>(p_hall, LDH, LDH1, p_meanh);

    k_att1<<<dim3(BS, 4), 384>>>();

    // batched layer-2 GEMM over 4 experts: 256 CTAs (128x128 tiles)
    k_gemm2<<<dim3(Ddim/128, BS/128, 4), 256>>>(mW2, dW2);

    k_s2d24  <<<(4*BS + 255)/256, 256>>>(ma2s, ma2d, da2s, da2d);
    k_colmean<<<(Bdim*LDH2 + 255)/256, 256>>>(p_h2all, LDH2, LDH2, p_meanh2);

    k_att2<<<dim3(BS, 4), 256>>>();

    k_final<<<1024, 256>>>(bbias, out);
    if (out_size >= BSD + 2) k_scalar<<<1, 256>>>(out);
}

// round 15
// speedup vs baseline: 1.2164x; 1.0205x over previous
#include <cuda_runtime.h>
#include <stdint.h>
#include <math.h>

// Problem constants (fixed by setup_inputs)
#define Bdim 4
#define Sdim 1024
#define Ddim 256
#define Hn   6
#define Hd   64
#define HF   384          // Hn*Hd
#define En   3
#define SENT_END 988      // S - sect - doc
#define SECT_END 1020     // S - doc
#define MAXDEG 256
#define BS  (Bdim*Sdim)   // 4096
#define BSD (BS*Ddim)     // 1048576
#define NBIG 1792         // 4*HF + Ddim  (4 experts layer-1 + blend)
#define LDH  1792         // g_hall row stride
#define LDH1 1536         // g_h1all row stride (4*HF)
#define LDH2 1024         // g_h2all row stride (4*Ddim)
#define ESN  (Bdim*Hn*Sdim)  // 24576 per expert

// ----------------------------- device scratch -----------------------------
__device__ __align__(128) int   g_nbr[BS*MAXDEG];
__device__ __align__(128) int   g_cnt[BS*3];
__device__ __align__(128) float g_mask[En*BS];
__device__ __align__(128) float g_Bpack[Ddim*NBIG];
__device__ __align__(128) float g_hall [BS*LDH];
__device__ __align__(128) float g_h1all[BS*LDH1];
__device__ __align__(128) float g_h2all[BS*LDH2];
__device__ __align__(128) float g_es[4*ESN];
__device__ __align__(128) float g_ed[4*ESN];
__device__ __align__(128) float g_s2[4*BS];
__device__ __align__(128) float g_d2[4*BS];
__device__ __align__(128) float g_main[BSD];
__device__ __align__(128) float g_dep3[En*BSD];
__device__ __align__(128) float g_meanh [Bdim*LDH1];
__device__ __align__(128) float g_meanh2[Bdim*LDH2];
__device__ __align__(128) float g_part[1024];

// packed fp32x2 FMA (Blackwell FFMA2 — only reachable via PTX)
__device__ __forceinline__ unsigned long long ffma2(
    unsigned long long a, unsigned long long b, unsigned long long c) {
    unsigned long long d;
    asm("fma.rn.f32x2 %0, %1, %2, %3;" : "=l"(d) : "l"(a), "l"(b), "l"(c));
    return d;
}
__device__ __forceinline__ unsigned long long dup2(float v) {
    unsigned u = __float_as_uint(v);
    return ((unsigned long long)u << 32) | u;
}
__device__ __forceinline__ float lo32(unsigned long long v) {
    return __uint_as_float((unsigned)(v & 0xffffffffull));
}
__device__ __forceinline__ float hi32(unsigned long long v) {
    return __uint_as_float((unsigned)(v >> 32));
}

// ----------------------------- kernels -----------------------------

// one warp per row: compact adjacency row into CSR (preserves ascending j order)
__global__ void k_build_csr(const float* __restrict__ adj) {
    int warp = (blockIdx.x*blockDim.x + threadIdx.x) >> 5;
    int lane = threadIdx.x & 31;
    if (warp >= BS) return;
    const float* row = adj + (size_t)warp * Sdim;
    int cnt = 0, c0 = 0, c1 = 0;
    for (int c = 0; c < Sdim; c += 32) {
        int j = c + lane;
        float v = row[j];
        unsigned m = __ballot_sync(0xffffffffu, v > 0.f);
        if (v > 0.f) {
            int pos = cnt + __popc(m & ((1u << lane) - 1u));
            if (pos < MAXDEG) g_nbr[warp*MAXDEG + pos] = j;
        }
        unsigned msent = __ballot_sync(0xffffffffu, j < SENT_END);
        unsigned msect = __ballot_sync(0xffffffffu, j < SECT_END);
        cnt += __popc(m);
        c0  += __popc(m & msent);
        c1  += __popc(m & msect);
    }
    if (lane == 0) {
        g_cnt[warp*3+0] = c0; g_cnt[warp*3+1] = c1; g_cnt[warp*3+2] = cnt;
    }
}

// one warp per node: router logits; top-2 of 3 == exclude argmin (ties -> larger idx)
__global__ void k_router(const float* __restrict__ x, const float* __restrict__ rw) {
    int warp = (blockIdx.x*blockDim.x + threadIdx.x) >> 5;
    int lane = threadIdx.x & 31;
    if (warp >= BS) return;
    const float* xp = x + (size_t)warp * Ddim;
    float l0 = 0.f, l1 = 0.f, l2 = 0.f;
    for (int d = lane; d < Ddim; d += 32) {
        float v = xp[d];
        l0 += v * rw[d*3+0];
        l1 += v * rw[d*3+1];
        l2 += v * rw[d*3+2];
    }
    for (int o = 16; o; o >>= 1) {
        l0 += __shfl_xor_sync(0xffffffffu, l0, o);
        l1 += __shfl_xor_sync(0xffffffffu, l1, o);
        l2 += __shfl_xor_sync(0xffffffffu, l2, o);
    }
    if (lane == 0) {
        int excl = 0; float mn = l0;
        if (l1 <= mn) { mn = l1; excl = 1; }
        if (l2 <= mn) { mn = l2; excl = 2; }
        g_mask[0*BS + warp] = (excl == 0) ? 0.f : 1.f;
        g_mask[1*BS + warp] = (excl == 1) ? 0.f : 1.f;
        g_mask[2*BS + warp] = (excl == 2) ? 0.f : 1.f;
    }
}

// build packed B [D=256 rows][NBIG=1792 cols]
__global__ void k_pack(const float* __restrict__ mW1, const float* __restrict__ dW1,
                       const float* __restrict__ bW) {
    int i = blockIdx.x*blockDim.x + threadIdx.x;
    if (i >= Ddim*NBIG) return;
    int f   = i / NBIG;
    int col = i - f*NBIG;
    float v;
    if (col < 4*HF) {
        int e  = col / HF;
        int ho = col - e*HF;
        int hh = ho >> 6, o = ho & 63;
        const float* src = (e == 0) ? mW1 : (dW1 + (size_t)(e-1)*Hn*Ddim*Hd);
        v = src[(hh*Ddim + f)*Hd + o];
    } else {
        v = bW[f*Ddim + (col - 4*HF)];
    }
    g_Bpack[i] = v;
}

// ---------------------------------------------------------------------------
// Fused big SGEMM: g_hall[4096,1792] = feature[4096,256] @ g_Bpack[256,1792]
// Tile 128x128, 256 threads, 8Mx8N micro-tile, double-buffered smem, FFMA2
// (accumulators packed along M; B lanes duplicated in registers).
// Column tiles: bx 0-2 main, 3-5 dep0, 6-8 dep1, 9-11 dep2, 12-13 blend.
// ---------------------------------------------------------------------------
__global__ void __launch_bounds__(256, 2) k_gemm_big(const float* __restrict__ A) {
    __shared__ __align__(16) float As[2][16][128];
    __shared__ __align__(16) float Bs[2][16][128];
    int tid = threadIdx.x;
    int tx = tid & 15;   // N micro (x8)
    int ty = tid >> 4;   // M micro (x8 = 4 f32x2 pairs)
    int bx = blockIdx.x; // N tile (0..13)
    int by = blockIdx.y; // M tile (0..31)
    const float* rowmask = nullptr;
    int seg = bx / 3;
    if (bx < 12 && seg > 0) rowmask = g_mask + (size_t)(seg-1)*BS;

    const float* Ab = A + (size_t)by*128*Ddim;
    const float* Bb = g_Bpack + bx*128;

    int ra0 = tid >> 2,         ca0 = (tid & 3) * 4;
    int ra1 = (tid + 256) >> 2, ca1 = ((tid + 256) & 3) * 4;
    int rb0 = tid >> 5,         cb0 = (tid & 31) * 4;
    int rb1 = (tid + 256) >> 5, cb1 = ((tid + 256) & 31) * 4;

    unsigned long long acc[4][8];
    #pragma unroll
    for (int i = 0; i < 4; i++)
        #pragma unroll
        for (int j = 0; j < 8; j++) acc[i][j] = 0ull;

    {   // stage 0
        float4 va0 = *(const float4*)(Ab + (size_t)ra0*Ddim + ca0);
        float4 va1 = *(const float4*)(Ab + (size_t)ra1*Ddim + ca1);
        float4 vb0 = *(const float4*)(Bb + (size_t)rb0*NBIG + cb0);
        float4 vb1 = *(const float4*)(Bb + (size_t)rb1*NBIG + cb1);
        As[0][ca0+0][ra0] = va0.x; As[0][ca0+1][ra0] = va0.y;
        As[0][ca0+2][ra0] = va0.z; As[0][ca0+3][ra0] = va0.w;
        As[0][ca1+0][ra1] = va1.x; As[0][ca1+1][ra1] = va1.y;
        As[0][ca1+2][ra1] = va1.z; As[0][ca1+3][ra1] = va1.w;
        *(float4*)&Bs[0][rb0][cb0] = vb0;
        *(float4*)&Bs[0][rb1][cb1] = vb1;
    }
    __syncthreads();

    const int nstage = Ddim / 16;   // 16
    for (int s = 0; s < nstage; s++) {
        int cur = s & 1, nxt = cur ^ 1;
        float4 pa0, pa1, pb0, pb1;
        bool has_next = (s + 1 < nstage);
        if (has_next) {
            int kn = (s + 1) * 16;
            pa0 = *(const float4*)(Ab + (size_t)ra0*Ddim + kn + ca0);
            pa1 = *(const float4*)(Ab + (size_t)ra1*Ddim + kn + ca1);
            pb0 = *(const float4*)(Bb + (size_t)(kn + rb0)*NBIG + cb0);
            pb1 = *(const float4*)(Bb + (size_t)(kn + rb1)*NBIG + cb1);
        }
        #pragma unroll
        for (int k = 0; k < 16; k++) {
            ulonglong2 a01 = *(const ulonglong2*)&As[cur][k][ty*8];
            ulonglong2 a23 = *(const ulonglong2*)&As[cur][k][ty*8+4];
            float4 b0 = *(const float4*)&Bs[cur][k][tx*8];
            float4 b1 = *(const float4*)&Bs[cur][k][tx*8+4];
            unsigned long long ap[4] = {a01.x, a01.y, a23.x, a23.y};
            float bs[8] = {b0.x,b0.y,b0.z,b0.w,b1.x,b1.y,b1.z,b1.w};
            #pragma unroll
            for (int j = 0; j < 8; j++) {
                unsigned long long bd = dup2(bs[j]);
                #pragma unroll
                for (int i = 0; i < 4; i++)
                    acc[i][j] = ffma2(ap[i], bd, acc[i][j]);
            }
        }
        if (has_next) {
            As[nxt][ca0+0][ra0] = pa0.x; As[nxt][ca0+1][ra0] = pa0.y;
            As[nxt][ca0+2][ra0] = pa0.z; As[nxt][ca0+3][ra0] = pa0.w;
            As[nxt][ca1+0][ra1] = pa1.x; As[nxt][ca1+1][ra1] = pa1.y;
            As[nxt][ca1+2][ra1] = pa1.z; As[nxt][ca1+3][ra1] = pa1.w;
            *(float4*)&Bs[nxt][rb0][cb0] = pb0;
            *(float4*)&Bs[nxt][rb1][cb1] = pb1;
        }
        __syncthreads();
    }

    #pragma unroll
    for (int mp = 0; mp < 4; mp++) {
        int row0 = by*128 + ty*8 + 2*mp;
        float mv0 = rowmask ? rowmask[row0]   : 1.f;
        float mv1 = rowmask ? rowmask[row0+1] : 1.f;
        float* c0 = g_hall + (size_t)row0*LDH     + bx*128 + tx*8;
        float* c1 = g_hall + (size_t)(row0+1)*LDH + bx*128 + tx*8;
        *(float4*)(c0)     = make_float4(lo32(acc[mp][0])*mv0, lo32(acc[mp][1])*mv0,
                                         lo32(acc[mp][2])*mv0, lo32(acc[mp][3])*mv0);
        *(float4*)(c0 + 4) = make_float4(lo32(acc[mp][4])*mv0, lo32(acc[mp][5])*mv0,
                                         lo32(acc[mp][6])*mv0, lo32(acc[mp][7])*mv0);
        *(float4*)(c1)     = make_float4(hi32(acc[mp][0])*mv1, hi32(acc[mp][1])*mv1,
                                         hi32(acc[mp][2])*mv1, hi32(acc[mp][3])*mv1);
        *(float4*)(c1 + 4) = make_float4(hi32(acc[mp][4])*mv1, hi32(acc[mp][5])*mv1,
                                         hi32(acc[mp][6])*mv1, hi32(acc[mp][7])*mv1);
    }
}

// ---------------------------------------------------------------------------
// Batched layer-2 SGEMM over blockIdx.z = expert, same FFMA2 128x128 tile.
// ---------------------------------------------------------------------------
__global__ void __launch_bounds__(256, 2) k_gemm2(const float* __restrict__ mW2,
                                                  const float* __restrict__ dW2) {
    __shared__ __align__(16) float As[2][16][128];
    __shared__ __align__(16) float Bs[2][16][128];
    int tid = threadIdx.x;
    int tx = tid & 15;
    int ty = tid >> 4;
    int bx = blockIdx.x;  // 0..1 (N=256)
    int by = blockIdx.y;  // 0..31
    int z  = blockIdx.z;  // expert
    const float* Ap = g_h1all + (size_t)z*HF;
    const float* Bp = (z == 0) ? mW2 : (dW2 + (size_t)(z-1)*HF*Ddim);
    const float* Ab = Ap + (size_t)by*128*LDH1;
    const float* Bb = Bp + bx*128;

    int ra0 = tid >> 2,         ca0 = (tid & 3) * 4;
    int ra1 = (tid + 256) >> 2, ca1 = ((tid + 256) & 3) * 4;
    int rb0 = tid >> 5,         cb0 = (tid & 31) * 4;
    int rb1 = (tid + 256) >> 5, cb1 = ((tid + 256) & 31) * 4;

    unsigned long long acc[4][8];
    #pragma unroll
    for (int i = 0; i < 4; i++)
        #pragma unroll
        for (int j = 0; j < 8; j++) acc[i][j] = 0ull;

    {
        float4 va0 = *(const float4*)(Ab + (size_t)ra0*LDH1 + ca0);
        float4 va1 = *(const float4*)(Ab + (size_t)ra1*LDH1 + ca1);
        float4 vb0 = *(const float4*)(Bb + (size_t)rb0*Ddim + cb0);
        float4 vb1 = *(const float4*)(Bb + (size_t)rb1*Ddim + cb1);
        As[0][ca0+0][ra0] = va0.x; As[0][ca0+1][ra0] = va0.y;
        As[0][ca0+2][ra0] = va0.z; As[0][ca0+3][ra0] = va0.w;
        As[0][ca1+0][ra1] = va1.x; As[0][ca1+1][ra1] = va1.y;
        As[0][ca1+2][ra1] = va1.z; As[0][ca1+3][ra1] = va1.w;
        *(float4*)&Bs[0][rb0][cb0] = vb0;
        *(float4*)&Bs[0][rb1][cb1] = vb1;
    }
    __syncthreads();

    const int nstage = HF / 16;   // 24
    for (int s = 0; s < nstage; s++) {
        int cur = s & 1, nxt = cur ^ 1;
        float4 pa0, pa1, pb0, pb1;
        bool has_next = (s + 1 < nstage);
        if (has_next) {
            int kn = (s + 1) * 16;
            pa0 = *(const float4*)(Ab + (size_t)ra0*LDH1 + kn + ca0);
            pa1 = *(const float4*)(Ab + (size_t)ra1*LDH1 + kn + ca1);
            pb0 = *(const float4*)(Bb + (size_t)(kn + rb0)*Ddim + cb0);
            pb1 = *(const float4*)(Bb + (size_t)(kn + rb1)*Ddim + cb1);
        }
        #pragma unroll
        for (int k = 0; k < 16; k++) {
            ulonglong2 a01 = *(const ulonglong2*)&As[cur][k][ty*8];
            ulonglong2 a23 = *(const ulonglong2*)&As[cur][k][ty*8+4];
            float4 b0 = *(const float4*)&Bs[cur][k][tx*8];
            float4 b1 = *(const float4*)&Bs[cur][k][tx*8+4];
            unsigned long long ap[4] = {a01.x, a01.y, a23.x, a23.y};
            float bs[8] = {b0.x,b0.y,b0.z,b0.w,b1.x,b1.y,b1.z,b1.w};
            #pragma unroll
            for (int j = 0; j < 8; j++) {
                unsigned long long bd = dup2(bs[j]);
                #pragma unroll
                for (int i = 0; i < 4; i++)
                    acc[i][j] = ffma2(ap[i], bd, acc[i][j]);
            }
        }
        if (has_next) {
            As[nxt][ca0+0][ra0] = pa0.x; As[nxt][ca0+1][ra0] = pa0.y;
            As[nxt][ca0+2][ra0] = pa0.z; As[nxt][ca0+3][ra0] = pa0.w;
            As[nxt][ca1+0][ra1] = pa1.x; As[nxt][ca1+1][ra1] = pa1.y;
            As[nxt][ca1+2][ra1] = pa1.z; As[nxt][ca1+3][ra1] = pa1.w;
            *(float4*)&Bs[nxt][rb0][cb0] = pb0;
            *(float4*)&Bs[nxt][rb1][cb1] = pb1;
        }
        __syncthreads();
    }

    #pragma unroll
    for (int mp = 0; mp < 4; mp++) {
        int row0 = by*128 + ty*8 + 2*mp;
        float* c0 = g_h2all + (size_t)row0*LDH2     + z*Ddim + bx*128 + tx*8;
        float* c1 = g_h2all + (size_t)(row0+1)*LDH2 + z*Ddim + bx*128 + tx*8;
        *(float4*)(c0)     = make_float4(lo32(acc[mp][0]), lo32(acc[mp][1]),
                                         lo32(acc[mp][2]), lo32(acc[mp][3]));
        *(float4*)(c0 + 4) = make_float4(lo32(acc[mp][4]), lo32(acc[mp][5]),
                                         lo32(acc[mp][6]), lo32(acc[mp][7]));
        *(float4*)(c1)     = make_float4(hi32(acc[mp][0]), hi32(acc[mp][1]),
                                         hi32(acc[mp][2]), hi32(acc[mp][3]));
        *(float4*)(c1 + 4) = make_float4(hi32(acc[mp][4]), hi32(acc[mp][5]),
                                         hi32(acc[mp][6]), hi32(acc[mp][7]));
    }
}

// batched es/ed projections for all 4 experts (float4 inner loop)
__global__ void k_esed4(const float* __restrict__ ma1s, const float* __restrict__ ma1d,
                        const float* __restrict__ da1s, const float* __restrict__ da1d) {
    int idx = blockIdx.x*blockDim.x + threadIdx.x;
    if (idx >= 4*ESN) return;
    int e = idx / ESN;
    int r = idx - e*ESN;
    int s  = r & (Sdim-1);
    int bh = r >> 10;
    int hh = bh % Hn;
    int b  = bh / Hn;
    const float4* hp = (const float4*)(g_hall + (size_t)(b*Sdim + s)*LDH + e*HF + hh*Hd);
    const float4* as = (const float4*)((((e == 0) ? ma1s : da1s + (e-1)*Hn*Hd)) + hh*Hd);
    const float4* ad = (const float4*)((((e == 0) ? ma1d : da1d + (e-1)*Hn*Hd)) + hh*Hd);
    float x = 0.f, y = 0.f;
    #pragma unroll
    for (int o = 0; o < Hd/4; o++) {
        float4 v = hp[o], a = as[o], d = ad[o];
        x += v.x*a.x + v.y*a.y + v.z*a.z + v.w*a.w;
        y += v.x*d.x + v.y*d.y + v.z*d.z + v.w*d.w;
    }
    g_es[idx] = x; g_ed[idx] = y;
}

// generic per-batch column mean
__global__ void k_colmean(const float* __restrict__ X, int ldx, int cols, float* __restrict__ out) {
    int idx = blockIdx.x*blockDim.x + threadIdx.x;
    if (idx >= Bdim*cols) return;
    int b = idx / cols, cc = idx - b*cols;
    const float* p = X + (size_t)b*Sdim*ldx + cc;
    float a0 = 0.f, a1 = 0.f, a2 = 0.f, a3 = 0.f;
    for (int r = 0; r < Sdim; r += 4) {
        a0 += p[(size_t)r*ldx];
        a1 += p[(size_t)(r+1)*ldx];
        a2 += p[(size_t)(r+2)*ldx];
        a3 += p[(size_t)(r+3)*ldx];
    }
    out[idx] = (a0 + a1 + a2 + a3) * (1.f/(float)Sdim);
}

// layer-1 sparse attention + ELU, batched: blockIdx.y = 0 main, 1..3 deputy.
__global__ void __launch_bounds__(384) k_att1(void) {
    int row = blockIdx.x;
    int ee  = blockIdx.y;
    int b = row >> 10, s = row & 1023;
    __shared__ float sc[Hn][MAXDEG];
    __shared__ int   snbr[MAXDEG];
    __shared__ float sden[Hn];
    __shared__ __align__(16) float4 red4[4][96];
    const int* c = g_cnt + row*3;
    int lo = 0, hi;
    if      (ee == 0) hi = c[2];
    else if (ee == 1) hi = c[0];
    else if (ee == 2) { lo = c[0]; hi = c[1]; }
    else              { lo = c[1]; hi = c[2]; }
    int deg = hi - lo;
    int tid = threadIdx.x;
    if (deg == 0) {
        for (int o = tid; o < HF; o += 384) {
            float v = g_meanh[b*LDH1 + ee*HF + o];
            g_h1all[(size_t)row*LDH1 + ee*HF + o] = (v > 0.f) ? v : expm1f(v);
        }
        return;
    }
    for (int j = tid; j < deg; j += 384) snbr[j] = g_nbr[row*MAXDEG + lo + j];
    __syncthreads();
    const float* esb = g_es + ee*ESN + b*Hn*Sdim;
    const float* edb = g_ed + ee*ESN + b*Hn*Sdim;
    for (int idx = tid; idx < Hn*deg; idx += 384) {
        int hh = idx / deg;
        int j  = idx - hh*deg;
        float v = esb[hh*Sdim + s] + edb[hh*Sdim + snbr[j]];
        sc[hh][j] = (v > 0.f) ? v : 0.2f*v;
    }
    __syncthreads();
    int warp = tid >> 5, lane = tid & 31;
    if (warp < Hn) {
        float m = -1e30f;
        for (int j = lane; j < deg; j += 32) m = fmaxf(m, sc[warp][j]);
        for (int o = 16; o; o >>= 1) m = fmaxf(m, __shfl_xor_sync(0xffffffffu, m, o));
        float su = 0.f;
        for (int j = lane; j < deg; j += 32) { float e = expf(sc[warp][j] - m); sc[warp][j] = e; su += e; }
        for (int o = 16; o; o >>= 1) su += __shfl_xor_sync(0xffffffffu, su, o);
        if (lane == 0) sden[warp] = su;
    }
    __syncthreads();
    int g  = tid / 96;
    int cq = tid - g*96;
    int cid = cq * 4;
    int hh = cid >> 6;
    const float* hb = g_hall + (size_t)(b*Sdim)*LDH + ee*HF + cid;
    float4 acc = make_float4(0.f, 0.f, 0.f, 0.f);
    #pragma unroll 2
    for (int j = g; j < deg; j += 4) {
        float w = sc[hh][j];
        float4 v = *(const float4*)(hb + (size_t)snbr[j]*LDH);
        acc.x += w*v.x; acc.y += w*v.y; acc.z += w*v.z; acc.w += w*v.w;
    }
    red4[g][cq] = acc;
    __syncthreads();
    if (tid < 96) {
        float4 a0 = red4[0][tid], a1 = red4[1][tid], a2 = red4[2][tid], a3 = red4[3][tid];
        int c0 = tid*4;
        float den = sden[c0 >> 6];
        float4 r;
        r.x = (a0.x + a1.x + a2.x + a3.x) / den;
        r.y = (a0.y + a1.y + a2.y + a3.y) / den;
        r.z = (a0.z + a1.z + a2.z + a3.z) / den;
        r.w = (a0.w + a1.w + a2.w + a3.w) / den;
        r.x = (r.x > 0.f) ? r.x : expm1f(r.x);
        r.y = (r.y > 0.f) ? r.y : expm1f(r.y);
        r.z = (r.z > 0.f) ? r.z : expm1f(r.z);
        r.w = (r.w > 0.f) ? r.w : expm1f(r.w);
        *(float4*)(g_h1all + (size_t)row*LDH1 + ee*HF + c0) = r;
    }
}

// batched layer-2 attention projections (float4 inner loop)
__global__ void k_s2d24(const float* __restrict__ ma2s, const float* __restrict__ ma2d,
                        const float* __restrict__ da2s, const float* __restrict__ da2d) {
    int idx = blockIdx.x*blockDim.x + threadIdx.x;
    if (idx >= 4*BS) return;
    int e   = idx / BS;
    int row = idx - e*BS;
    const float4* p  = (const float4*)(g_h2all + (size_t)row*LDH2 + e*Ddim);
    const float4* as = (const float4*)((e == 0) ? ma2s : da2s + (e-1)*Ddim);
    const float4* ad = (const float4*)((e == 0) ? ma2d : da2d + (e-1)*Ddim);
    float x = 0.f, y = 0.f;
    #pragma unroll 4
    for (int d = 0; d < Ddim/4; d++) {
        float4 v = p[d], a = as[d], dd = ad[d];
        x += v.x*a.x + v.y*a.y + v.z*a.z + v.w*a.w;
        y += v.x*dd.x + v.y*dd.y + v.z*dd.z + v.w*dd.w;
    }
    g_s2[idx] = x; g_d2[idx] = y;
}

// layer-2 sparse attention, batched: y=0 main -> g_main; y=1..3 -> g_dep3[e]
__global__ void __launch_bounds__(256) k_att2(void) {
    int row = blockIdx.x;
    int ee  = blockIdx.y;
    if (ee > 0 && g_mask[(ee-1)*BS + row] == 0.f) return;
    int b = row >> 10;
    __shared__ float sc[MAXDEG];
    __shared__ int   snbr[MAXDEG];
    __shared__ float sden;
    __shared__ __align__(16) float4 red4[4][64];
    const int* c = g_cnt + row*3;
    int lo = 0, hi;
    if      (ee == 0) hi = c[2];
    else if (ee == 1) hi = c[0];
    else if (ee == 2) { lo = c[0]; hi = c[1]; }
    else              { lo = c[1]; hi = c[2]; }
    int deg = hi - lo;
    int tid = threadIdx.x;
    float* outp = (ee == 0) ? (g_main + (size_t)row*Ddim)
                            : (g_dep3 + (size_t)(ee-1)*BSD + (size_t)row*Ddim);
    if (deg == 0) {
        for (int o = tid; o < Ddim; o += 256)
            outp[o] = g_meanh2[b*LDH2 + ee*Ddim + o];
        return;
    }
    for (int j = tid; j < deg; j += 256) snbr[j] = g_nbr[row*MAXDEG + lo + j];
    __syncthreads();
    float srcsc = g_s2[ee*BS + row];
    const float* d2b = g_d2 + ee*BS + b*Sdim;
    for (int j = tid; j < deg; j += 256) {
        float v = srcsc + d2b[snbr[j]];
        sc[j] = (v > 0.f) ? v : 0.2f*v;
    }
    __syncthreads();
    if (tid < 32) {
        float m = -1e30f;
        for (int j = tid; j < deg; j += 32) m = fmaxf(m, sc[j]);
        for (int o = 16; o; o >>= 1) m = fmaxf(m, __shfl_xor_sync(0xffffffffu, m, o));
        float su = 0.f;
        for (int j = tid; j < deg; j += 32) { float e = expf(sc[j] - m); sc[j] = e; su += e; }
        for (int o = 16; o; o >>= 1) su += __shfl_xor_sync(0xffffffffu, su, o);
        if (tid == 0) sden = su;
    }
    __syncthreads();
    int g  = tid >> 6;
    int cq = tid & 63;
    int cid = cq * 4;
    const float* hb = g_h2all + (size_t)(b*Sdim)*LDH2 + ee*Ddim + cid;
    float4 acc = make_float4(0.f, 0.f, 0.f, 0.f);
    #pragma unroll 2
    for (int j = g; j < deg; j += 4) {
        float w = sc[j];
        float4 v = *(const float4*)(hb + (size_t)snbr[j]*LDH2);
        acc.x += w*v.x; acc.y += w*v.y; acc.z += w*v.z; acc.w += w*v.w;
    }
    red4[g][cq] = acc;
    __syncthreads();
    if (tid < 64) {
        float4 a0 = red4[0][tid], a1 = red4[1][tid], a2 = red4[2][tid], a3 = red4[3][tid];
        float den = sden;
        float4 r;
        r.x = (a0.x + a1.x + a2.x + a3.x) / den;
        r.y = (a0.y + a1.y + a2.y + a3.y) / den;
        r.z = (a0.z + a1.z + a2.z + a3.z) / den;
        r.w = (a0.w + a1.w + a2.w + a3.w) / den;
        *(float4*)(outp + tid*4) = r;
    }
}

// blend + final output + deterministic partial sums of blend weights
__global__ void __launch_bounds__(256) k_final(const float* __restrict__ bbias, float* __restrict__ out) {
    __shared__ float red[256];
    int t = threadIdx.x;
    int base = blockIdx.x*1024;
    float s = 0.f;
    #pragma unroll
    for (int l = 0; l < 4; l++) {
        int i   = base + l*256 + t;
        int row = i >> 8;
        int d   = i & (Ddim-1);
        float blendv = g_hall[(size_t)row*LDH + 4*HF + d];
        float w = 1.f / (1.f + expf(-(blendv + bbias[d])));
        float dep = g_mask[0*BS + row] * g_dep3[0*BSD + i]
                  + g_mask[1*BS + row] * g_dep3[1*BSD + i]
                  + g_mask[2*BS + row] * g_dep3[2*BSD + i];
        out[i] = w*g_main[i] + (1.f - w)*dep;
        s += w;
    }
    red[t] = s; __syncthreads();
    for (int o = 128; o; o >>= 1) { if (t < o) red[t] += red[t+o]; __syncthreads(); }
    if (t == 0) g_part[blockIdx.x] = red[0];
}

__global__ void k_scalar(float* __restrict__ out) {
    __shared__ float red[256];
    int t = threadIdx.x;
    float s = 0.f;
    for (int i = t; i < 1024; i += 256) s += g_part[i];
    red[t] = s; __syncthreads();
    for (int o = 128; o; o >>= 1) { if (t < o) red[t] += red[t+o]; __syncthreads(); }
    if (t == 0) {
        float mc = red[0] / (float)BSD;
        out[BSD]     = fabsf(mc - 0.6f) * 0.01f;
        out[BSD + 1] = mc;
    }
}

// ----------------------------- host launcher -----------------------------
extern "C" void kernel_launch(void* const* d_in, const int* in_sizes, int n_in,
                              void* d_out, int out_size) {
    const float* feature = (const float*)d_in[0];
    const float* adj     = (const float*)d_in[1];
    const float* mW1     = (const float*)d_in[2];
    const float* ma1s    = (const float*)d_in[3];
    const float* ma1d    = (const float*)d_in[4];
    const float* mW2     = (const float*)d_in[5];
    const float* ma2s    = (const float*)d_in[6];
    const float* ma2d    = (const float*)d_in[7];
    const float* dW1     = (const float*)d_in[8];
    const float* da1s    = (const float*)d_in[9];
    const float* da1d    = (const float*)d_in[10];
    const float* dW2     = (const float*)d_in[11];
    const float* da2s    = (const float*)d_in[12];
    const float* da2d    = (const float*)d_in[13];
    const float* rW      = (const float*)d_in[14];
    const float* bW      = (const float*)d_in[15];
    const float* bbias   = (const float*)d_in[16];
    float* out = (float*)d_out;

    static float *p_hall = nullptr, *p_h2all, *p_meanh, *p_meanh2;
    if (!p_hall) {
        cudaGetSymbolAddress((void**)&p_hall,   g_hall);
        cudaGetSymbolAddress((void**)&p_h2all,  g_h2all);
        cudaGetSymbolAddress((void**)&p_meanh,  g_meanh);
        cudaGetSymbolAddress((void**)&p_meanh2, g_meanh2);
    }

    k_router   <<<512, 256>>>(feature, rW);
    k_build_csr<<<512, 256>>>(adj);
    k_pack     <<<(Ddim*NBIG + 255)/256, 256>>>(mW1, dW1, bW);

    // fused layer-1 (4 experts) + blend GEMM: 448 CTAs (128x128 FFMA2 tiles)
    k_gemm_big<<<dim3(NBIG/128, BS/128), 256>>>(feature);

    k_esed4  <<<(4*ESN + 255)/256, 256>>>(ma1s, ma1d, da1s, da1d);
    k_colmean<<<(Bdim*LDH1 + 255)/256, 256>>>(p_hall, LDH, LDH1, p_meanh);

    k_att1<<<dim3(BS, 4), 384>>>();

    // batched layer-2 GEMM over 4 experts: 256 CTAs (128x128 FFMA2 tiles)
    k_gemm2<<<dim3(Ddim/128, BS/128, 4), 256>>>(mW2, dW2);

    k_s2d24  <<<(4*BS + 255)/256, 256>>>(ma2s, ma2d, da2s, da2d);
    k_colmean<<<(Bdim*LDH2 + 255)/256, 256>>>(p_h2all, LDH2, LDH2, p_meanh2);

    k_att2<<<dim3(BS, 4), 256>>>();

    k_final<<<1024, 256>>>(bbias, out);
    if (out_size >= BSD + 2) k_scalar<<<1, 256>>>(out);
}

// round 16
// speedup vs baseline: 1.3672x; 1.1240x over previous
#include <cuda_runtime.h>
#include <stdint.h>
#include <math.h>

// Problem constants (fixed by setup_inputs)
#define Bdim 4
#define Sdim 1024
#define Ddim 256
#define Hn   6
#define Hd   64
#define HF   384          // Hn*Hd
#define En   3
#define SENT_END 988      // S - sect - doc
#define SECT_END 1020     // S - doc
#define MAXDEG 256
#define BS  (Bdim*Sdim)   // 4096
#define BSD (BS*Ddim)     // 1048576
#define NBIG 1792         // 4*HF + Ddim  (4 experts layer-1 + blend)
#define LDH  1792         // g_hall row stride
#define LDH1 1536         // g_h1all row stride (4*HF)
#define LDH2 1024         // g_h2all row stride (4*Ddim)
#define ESN  (Bdim*Hn*Sdim)  // 24576 per expert

// ----------------------------- device scratch -----------------------------
__device__ __align__(128) int   g_nbr[BS*MAXDEG];
__device__ __align__(128) int   g_cnt[BS*3];
__device__ __align__(128) float g_mask[En*BS];
__device__ __align__(128) float g_Bpack[Ddim*NBIG];
__device__ __align__(128) float g_hall [BS*LDH];
__device__ __align__(128) float g_h1all[BS*LDH1];
__device__ __align__(128) float g_h2all[BS*LDH2];
__device__ __align__(128) float g_es[4*ESN];
__device__ __align__(128) float g_ed[4*ESN];
__device__ __align__(128) float g_s2[4*BS];
__device__ __align__(128) float g_d2[4*BS];
__device__ __align__(128) float g_main[BSD];
__device__ __align__(128) float g_dep3[En*BSD];
__device__ __align__(128) float g_meanh [Bdim*LDH1];
__device__ __align__(128) float g_meanh2[Bdim*LDH2];
__device__ __align__(128) float g_part[1024];

// packed fp32x2 FMA (Blackwell FFMA2 — only reachable via PTX)
__device__ __forceinline__ unsigned long long ffma2(
    unsigned long long a, unsigned long long b, unsigned long long c) {
    unsigned long long d;
    asm("fma.rn.f32x2 %0, %1, %2, %3;" : "=l"(d) : "l"(a), "l"(b), "l"(c));
    return d;
}
__device__ __forceinline__ unsigned long long dup2(float v) {
    unsigned u = __float_as_uint(v);
    return ((unsigned long long)u << 32) | u;
}
__device__ __forceinline__ float lo32(unsigned long long v) {
    return __uint_as_float((unsigned)(v & 0xffffffffull));
}
__device__ __forceinline__ float hi32(unsigned long long v) {
    return __uint_as_float((unsigned)(v >> 32));
}

// ----------------------------- kernels -----------------------------

// one warp per row: compact adjacency row into CSR (preserves ascending j order)
__global__ void k_build_csr(const float* __restrict__ adj) {
    int warp = (blockIdx.x*blockDim.x + threadIdx.x) >> 5;
    int lane = threadIdx.x & 31;
    if (warp >= BS) return;
    const float* row = adj + (size_t)warp * Sdim;
    int cnt = 0, c0 = 0, c1 = 0;
    for (int c = 0; c < Sdim; c += 32) {
        int j = c + lane;
        float v = row[j];
        unsigned m = __ballot_sync(0xffffffffu, v > 0.f);
        if (v > 0.f) {
            int pos = cnt + __popc(m & ((1u << lane) - 1u));
            if (pos < MAXDEG) g_nbr[warp*MAXDEG + pos] = j;
        }
        unsigned msent = __ballot_sync(0xffffffffu, j < SENT_END);
        unsigned msect = __ballot_sync(0xffffffffu, j < SECT_END);
        cnt += __popc(m);
        c0  += __popc(m & msent);
        c1  += __popc(m & msect);
    }
    if (lane == 0) {
        g_cnt[warp*3+0] = c0; g_cnt[warp*3+1] = c1; g_cnt[warp*3+2] = cnt;
    }
}

// one warp per node: router logits; top-2 of 3 == exclude argmin (ties -> larger idx)
__global__ void k_router(const float* __restrict__ x, const float* __restrict__ rw) {
    int warp = (blockIdx.x*blockDim.x + threadIdx.x) >> 5;
    int lane = threadIdx.x & 31;
    if (warp >= BS) return;
    const float* xp = x + (size_t)warp * Ddim;
    float l0 = 0.f, l1 = 0.f, l2 = 0.f;
    for (int d = lane; d < Ddim; d += 32) {
        float v = xp[d];
        l0 += v * rw[d*3+0];
        l1 += v * rw[d*3+1];
        l2 += v * rw[d*3+2];
    }
    for (int o = 16; o; o >>= 1) {
        l0 += __shfl_xor_sync(0xffffffffu, l0, o);
        l1 += __shfl_xor_sync(0xffffffffu, l1, o);
        l2 += __shfl_xor_sync(0xffffffffu, l2, o);
    }
    if (lane == 0) {
        int excl = 0; float mn = l0;
        if (l1 <= mn) { mn = l1; excl = 1; }
        if (l2 <= mn) { mn = l2; excl = 2; }
        g_mask[0*BS + warp] = (excl == 0) ? 0.f : 1.f;
        g_mask[1*BS + warp] = (excl == 1) ? 0.f : 1.f;
        g_mask[2*BS + warp] = (excl == 2) ? 0.f : 1.f;
    }
}

// build packed B [D=256 rows][NBIG=1792 cols]
__global__ void k_pack(const float* __restrict__ mW1, const float* __restrict__ dW1,
                       const float* __restrict__ bW) {
    int i = blockIdx.x*blockDim.x + threadIdx.x;
    if (i >= Ddim*NBIG) return;
    int f   = i / NBIG;
    int col = i - f*NBIG;
    float v;
    if (col < 4*HF) {
        int e  = col / HF;
        int ho = col - e*HF;
        int hh = ho >> 6, o = ho & 63;
        const float* src = (e == 0) ? mW1 : (dW1 + (size_t)(e-1)*Hn*Ddim*Hd);
        v = src[(hh*Ddim + f)*Hd + o];
    } else {
        v = bW[f*Ddim + (col - 4*HF)];
    }
    g_Bpack[i] = v;
}

// ---------------------------------------------------------------------------
// Fused big SGEMM: g_hall[4096,1792] = feature[4096,256] @ g_Bpack[256,1792]
// Tile 128x128, 256 threads, 8Mx8N micro-tile, double-buffered smem, FFMA2.
// ---------------------------------------------------------------------------
__global__ void __launch_bounds__(256, 2) k_gemm_big(const float* __restrict__ A) {
    __shared__ __align__(16) float As[2][16][128];
    __shared__ __align__(16) float Bs[2][16][128];
    int tid = threadIdx.x;
    int tx = tid & 15;   // N micro (x8)
    int ty = tid >> 4;   // M micro (x8 = 4 f32x2 pairs)
    int bx = blockIdx.x; // N tile (0..13)
    int by = blockIdx.y; // M tile (0..31)
    const float* rowmask = nullptr;
    int seg = bx / 3;
    if (bx < 12 && seg > 0) rowmask = g_mask + (size_t)(seg-1)*BS;

    const float* Ab = A + (size_t)by*128*Ddim;
    const float* Bb = g_Bpack + bx*128;

    int ra0 = tid >> 2,         ca0 = (tid & 3) * 4;
    int ra1 = (tid + 256) >> 2, ca1 = ((tid + 256) & 3) * 4;
    int rb0 = tid >> 5,         cb0 = (tid & 31) * 4;
    int rb1 = (tid + 256) >> 5, cb1 = ((tid + 256) & 31) * 4;

    unsigned long long acc[4][8];
    #pragma unroll
    for (int i = 0; i < 4; i++)
        #pragma unroll
        for (int j = 0; j < 8; j++) acc[i][j] = 0ull;

    {   // stage 0
        float4 va0 = *(const float4*)(Ab + (size_t)ra0*Ddim + ca0);
        float4 va1 = *(const float4*)(Ab + (size_t)ra1*Ddim + ca1);
        float4 vb0 = *(const float4*)(Bb + (size_t)rb0*NBIG + cb0);
        float4 vb1 = *(const float4*)(Bb + (size_t)rb1*NBIG + cb1);
        As[0][ca0+0][ra0] = va0.x; As[0][ca0+1][ra0] = va0.y;
        As[0][ca0+2][ra0] = va0.z; As[0][ca0+3][ra0] = va0.w;
        As[0][ca1+0][ra1] = va1.x; As[0][ca1+1][ra1] = va1.y;
        As[0][ca1+2][ra1] = va1.z; As[0][ca1+3][ra1] = va1.w;
        *(float4*)&Bs[0][rb0][cb0] = vb0;
        *(float4*)&Bs[0][rb1][cb1] = vb1;
    }
    __syncthreads();

    const int nstage = Ddim / 16;   // 16
    for (int s = 0; s < nstage; s++) {
        int cur = s & 1, nxt = cur ^ 1;
        float4 pa0, pa1, pb0, pb1;
        bool has_next = (s + 1 < nstage);
        if (has_next) {
            int kn = (s + 1) * 16;
            pa0 = *(const float4*)(Ab + (size_t)ra0*Ddim + kn + ca0);
            pa1 = *(const float4*)(Ab + (size_t)ra1*Ddim + kn + ca1);
            pb0 = *(const float4*)(Bb + (size_t)(kn + rb0)*NBIG + cb0);
            pb1 = *(const float4*)(Bb + (size_t)(kn + rb1)*NBIG + cb1);
        }
        #pragma unroll
        for (int k = 0; k < 16; k++) {
            ulonglong2 a01 = *(const ulonglong2*)&As[cur][k][ty*8];
            ulonglong2 a23 = *(const ulonglong2*)&As[cur][k][ty*8+4];
            float4 b0 = *(const float4*)&Bs[cur][k][tx*8];
            float4 b1 = *(const float4*)&Bs[cur][k][tx*8+4];
            unsigned long long ap[4] = {a01.x, a01.y, a23.x, a23.y};
            float bs[8] = {b0.x,b0.y,b0.z,b0.w,b1.x,b1.y,b1.z,b1.w};
            #pragma unroll
            for (int j = 0; j < 8; j++) {
                unsigned long long bd = dup2(bs[j]);
                #pragma unroll
                for (int i = 0; i < 4; i++)
                    acc[i][j] = ffma2(ap[i], bd, acc[i][j]);
            }
        }
        if (has_next) {
            As[nxt][ca0+0][ra0] = pa0.x; As[nxt][ca0+1][ra0] = pa0.y;
            As[nxt][ca0+2][ra0] = pa0.z; As[nxt][ca0+3][ra0] = pa0.w;
            As[nxt][ca1+0][ra1] = pa1.x; As[nxt][ca1+1][ra1] = pa1.y;
            As[nxt][ca1+2][ra1] = pa1.z; As[nxt][ca1+3][ra1] = pa1.w;
            *(float4*)&Bs[nxt][rb0][cb0] = pb0;
            *(float4*)&Bs[nxt][rb1][cb1] = pb1;
        }
        __syncthreads();
    }

    #pragma unroll
    for (int mp = 0; mp < 4; mp++) {
        int row0 = by*128 + ty*8 + 2*mp;
        float mv0 = rowmask ? rowmask[row0]   : 1.f;
        float mv1 = rowmask ? rowmask[row0+1] : 1.f;
        float* c0 = g_hall + (size_t)row0*LDH     + bx*128 + tx*8;
        float* c1 = g_hall + (size_t)(row0+1)*LDH + bx*128 + tx*8;
        *(float4*)(c0)     = make_float4(lo32(acc[mp][0])*mv0, lo32(acc[mp][1])*mv0,
                                         lo32(acc[mp][2])*mv0, lo32(acc[mp][3])*mv0);
        *(float4*)(c0 + 4) = make_float4(lo32(acc[mp][4])*mv0, lo32(acc[mp][5])*mv0,
                                         lo32(acc[mp][6])*mv0, lo32(acc[mp][7])*mv0);
        *(float4*)(c1)     = make_float4(hi32(acc[mp][0])*mv1, hi32(acc[mp][1])*mv1,
                                         hi32(acc[mp][2])*mv1, hi32(acc[mp][3])*mv1);
        *(float4*)(c1 + 4) = make_float4(hi32(acc[mp][4])*mv1, hi32(acc[mp][5])*mv1,
                                         hi32(acc[mp][6])*mv1, hi32(acc[mp][7])*mv1);
    }
}

// ---------------------------------------------------------------------------
// Batched layer-2 SGEMM over blockIdx.z = expert, same FFMA2 128x128 tile.
// ---------------------------------------------------------------------------
__global__ void __launch_bounds__(256, 2) k_gemm2(const float* __restrict__ mW2,
                                                  const float* __restrict__ dW2) {
    __shared__ __align__(16) float As[2][16][128];
    __shared__ __align__(16) float Bs[2][16][128];
    int tid = threadIdx.x;
    int tx = tid & 15;
    int ty = tid >> 4;
    int bx = blockIdx.x;  // 0..1 (N=256)
    int by = blockIdx.y;  // 0..31
    int z  = blockIdx.z;  // expert
    const float* Ap = g_h1all + (size_t)z*HF;
    const float* Bp = (z == 0) ? mW2 : (dW2 + (size_t)(z-1)*HF*Ddim);
    const float* Ab = Ap + (size_t)by*128*LDH1;
    const float* Bb = Bp + bx*128;

    int ra0 = tid >> 2,         ca0 = (tid & 3) * 4;
    int ra1 = (tid + 256) >> 2, ca1 = ((tid + 256) & 3) * 4;
    int rb0 = tid >> 5,         cb0 = (tid & 31) * 4;
    int rb1 = (tid + 256) >> 5, cb1 = ((tid + 256) & 31) * 4;

    unsigned long long acc[4][8];
    #pragma unroll
    for (int i = 0; i < 4; i++)
        #pragma unroll
        for (int j = 0; j < 8; j++) acc[i][j] = 0ull;

    {
        float4 va0 = *(const float4*)(Ab + (size_t)ra0*LDH1 + ca0);
        float4 va1 = *(const float4*)(Ab + (size_t)ra1*LDH1 + ca1);
        float4 vb0 = *(const float4*)(Bb + (size_t)rb0*Ddim + cb0);
        float4 vb1 = *(const float4*)(Bb + (size_t)rb1*Ddim + cb1);
        As[0][ca0+0][ra0] = va0.x; As[0][ca0+1][ra0] = va0.y;
        As[0][ca0+2][ra0] = va0.z; As[0][ca0+3][ra0] = va0.w;
        As[0][ca1+0][ra1] = va1.x; As[0][ca1+1][ra1] = va1.y;
        As[0][ca1+2][ra1] = va1.z; As[0][ca1+3][ra1] = va1.w;
        *(float4*)&Bs[0][rb0][cb0] = vb0;
        *(float4*)&Bs[0][rb1][cb1] = vb1;
    }
    __syncthreads();

    const int nstage = HF / 16;   // 24
    for (int s = 0; s < nstage; s++) {
        int cur = s & 1, nxt = cur ^ 1;
        float4 pa0, pa1, pb0, pb1;
        bool has_next = (s + 1 < nstage);
        if (has_next) {
            int kn = (s + 1) * 16;
            pa0 = *(const float4*)(Ab + (size_t)ra0*LDH1 + kn + ca0);
            pa1 = *(const float4*)(Ab + (size_t)ra1*LDH1 + kn + ca1);
            pb0 = *(const float4*)(Bb + (size_t)(kn + rb0)*Ddim + cb0);
            pb1 = *(const float4*)(Bb + (size_t)(kn + rb1)*Ddim + cb1);
        }
        #pragma unroll
        for (int k = 0; k < 16; k++) {
            ulonglong2 a01 = *(const ulonglong2*)&As[cur][k][ty*8];
            ulonglong2 a23 = *(const ulonglong2*)&As[cur][k][ty*8+4];
            float4 b0 = *(const float4*)&Bs[cur][k][tx*8];
            float4 b1 = *(const float4*)&Bs[cur][k][tx*8+4];
            unsigned long long ap[4] = {a01.x, a01.y, a23.x, a23.y};
            float bs[8] = {b0.x,b0.y,b0.z,b0.w,b1.x,b1.y,b1.z,b1.w};
            #pragma unroll
            for (int j = 0; j < 8; j++) {
                unsigned long long bd = dup2(bs[j]);
                #pragma unroll
                for (int i = 0; i < 4; i++)
                    acc[i][j] = ffma2(ap[i], bd, acc[i][j]);
            }
        }
        if (has_next) {
            As[nxt][ca0+0][ra0] = pa0.x; As[nxt][ca0+1][ra0] = pa0.y;
            As[nxt][ca0+2][ra0] = pa0.z; As[nxt][ca0+3][ra0] = pa0.w;
            As[nxt][ca1+0][ra1] = pa1.x; As[nxt][ca1+1][ra1] = pa1.y;
            As[nxt][ca1+2][ra1] = pa1.z; As[nxt][ca1+3][ra1] = pa1.w;
            *(float4*)&Bs[nxt][rb0][cb0] = pb0;
            *(float4*)&Bs[nxt][rb1][cb1] = pb1;
        }
        __syncthreads();
    }

    #pragma unroll
    for (int mp = 0; mp < 4; mp++) {
        int row0 = by*128 + ty*8 + 2*mp;
        float* c0 = g_h2all + (size_t)row0*LDH2     + z*Ddim + bx*128 + tx*8;
        float* c1 = g_h2all + (size_t)(row0+1)*LDH2 + z*Ddim + bx*128 + tx*8;
        *(float4*)(c0)     = make_float4(lo32(acc[mp][0]), lo32(acc[mp][1]),
                                         lo32(acc[mp][2]), lo32(acc[mp][3]));
        *(float4*)(c0 + 4) = make_float4(lo32(acc[mp][4]), lo32(acc[mp][5]),
                                         lo32(acc[mp][6]), lo32(acc[mp][7]));
        *(float4*)(c1)     = make_float4(hi32(acc[mp][0]), hi32(acc[mp][1]),
                                         hi32(acc[mp][2]), hi32(acc[mp][3]));
        *(float4*)(c1 + 4) = make_float4(hi32(acc[mp][4]), hi32(acc[mp][5]),
                                         hi32(acc[mp][6]), hi32(acc[mp][7]));
    }
}

// batched es/ed projections for all 4 experts (float4 inner loop)
__global__ void k_esed4(const float* __restrict__ ma1s, const float* __restrict__ ma1d,
                        const float* __restrict__ da1s, const float* __restrict__ da1d) {
    int idx = blockIdx.x*blockDim.x + threadIdx.x;
    if (idx >= 4*ESN) return;
    int e = idx / ESN;
    int r = idx - e*ESN;
    int s  = r & (Sdim-1);
    int bh = r >> 10;
    int hh = bh % Hn;
    int b  = bh / Hn;
    const float4* hp = (const float4*)(g_hall + (size_t)(b*Sdim + s)*LDH + e*HF + hh*Hd);
    const float4* as = (const float4*)((((e == 0) ? ma1s : da1s + (e-1)*Hn*Hd)) + hh*Hd);
    const float4* ad = (const float4*)((((e == 0) ? ma1d : da1d + (e-1)*Hn*Hd)) + hh*Hd);
    float x = 0.f, y = 0.f;
    #pragma unroll
    for (int o = 0; o < Hd/4; o++) {
        float4 v = hp[o], a = as[o], d = ad[o];
        x += v.x*a.x + v.y*a.y + v.z*a.z + v.w*a.w;
        y += v.x*d.x + v.y*d.y + v.z*d.z + v.w*d.w;
    }
    g_es[idx] = x; g_ed[idx] = y;
}

// per-batch column mean, parallelized over rows:
// block = 32 cols x 8 row-groups (128 rows each); grid = Bdim * cols/32
__global__ void __launch_bounds__(256) k_colmean(const float* __restrict__ X, int ldx,
                                                 int cols, float* __restrict__ out) {
    __shared__ float red[8][32];
    int blocksPerB = cols >> 5;
    int b  = blockIdx.x / blocksPerB;
    int cb = (blockIdx.x - b*blocksPerB) << 5;
    int cl = threadIdx.x & 31;
    int rg = threadIdx.x >> 5;      // 0..7
    const float* p = X + (size_t)b*Sdim*ldx + cb + cl;
    float a0 = 0.f, a1 = 0.f, a2 = 0.f, a3 = 0.f;
    int r0 = rg*128;
    for (int r = r0; r < r0 + 128; r += 4) {
        a0 += p[(size_t)r*ldx];
        a1 += p[(size_t)(r+1)*ldx];
        a2 += p[(size_t)(r+2)*ldx];
        a3 += p[(size_t)(r+3)*ldx];
    }
    red[rg][cl] = (a0 + a1) + (a2 + a3);
    __syncthreads();
    if (rg == 0) {
        float t = 0.f;
        #pragma unroll
        for (int i = 0; i < 8; i++) t += red[i][cl];
        out[b*cols + cb + cl] = t * (1.f/(float)Sdim);
    }
}

// layer-1 sparse attention + ELU, batched: blockIdx.y = 0 main, 1..3 deputy.
__global__ void __launch_bounds__(384) k_att1(void) {
    int row = blockIdx.x;
    int ee  = blockIdx.y;
    int b = row >> 10, s = row & 1023;
    __shared__ float sc[Hn][MAXDEG];
    __shared__ int   snbr[MAXDEG];
    __shared__ float sden[Hn];
    __shared__ __align__(16) float4 red4[4][96];
    const int* c = g_cnt + row*3;
    int lo = 0, hi;
    if      (ee == 0) hi = c[2];
    else if (ee == 1) hi = c[0];
    else if (ee == 2) { lo = c[0]; hi = c[1]; }
    else              { lo = c[1]; hi = c[2]; }
    int deg = hi - lo;
    int tid = threadIdx.x;
    if (deg == 0) {
        for (int o = tid; o < HF; o += 384) {
            float v = g_meanh[b*LDH1 + ee*HF + o];
            g_h1all[(size_t)row*LDH1 + ee*HF + o] = (v > 0.f) ? v : expm1f(v);
        }
        return;
    }
    for (int j = tid; j < deg; j += 384) snbr[j] = g_nbr[row*MAXDEG + lo + j];
    __syncthreads();
    const float* esb = g_es + ee*ESN + b*Hn*Sdim;
    const float* edb = g_ed + ee*ESN + b*Hn*Sdim;
    for (int idx = tid; idx < Hn*deg; idx += 384) {
        int hh = idx / deg;
        int j  = idx - hh*deg;
        float v = esb[hh*Sdim + s] + edb[hh*Sdim + snbr[j]];
        sc[hh][j] = (v > 0.f) ? v : 0.2f*v;
    }
    __syncthreads();
    int warp = tid >> 5, lane = tid & 31;
    if (warp < Hn) {
        float m = -1e30f;
        for (int j = lane; j < deg; j += 32) m = fmaxf(m, sc[warp][j]);
        for (int o = 16; o; o >>= 1) m = fmaxf(m, __shfl_xor_sync(0xffffffffu, m, o));
        float su = 0.f;
        for (int j = lane; j < deg; j += 32) { float e = expf(sc[warp][j] - m); sc[warp][j] = e; su += e; }
        for (int o = 16; o; o >>= 1) su += __shfl_xor_sync(0xffffffffu, su, o);
        if (lane == 0) sden[warp] = su;
    }
    __syncthreads();
    int g  = tid / 96;
    int cq = tid - g*96;
    int cid = cq * 4;
    int hh = cid >> 6;
    const float* hb = g_hall + (size_t)(b*Sdim)*LDH + ee*HF + cid;
    float4 acc = make_float4(0.f, 0.f, 0.f, 0.f);
    #pragma unroll 2
    for (int j = g; j < deg; j += 4) {
        float w = sc[hh][j];
        float4 v = *(const float4*)(hb + (size_t)snbr[j]*LDH);
        acc.x += w*v.x; acc.y += w*v.y; acc.z += w*v.z; acc.w += w*v.w;
    }
    red4[g][cq] = acc;
    __syncthreads();
    if (tid < 96) {
        float4 a0 = red4[0][tid], a1 = red4[1][tid], a2 = red4[2][tid], a3 = red4[3][tid];
        int c0 = tid*4;
        float den = sden[c0 >> 6];
        float4 r;
        r.x = (a0.x + a1.x + a2.x + a3.x) / den;
        r.y = (a0.y + a1.y + a2.y + a3.y) / den;
        r.z = (a0.z + a1.z + a2.z + a3.z) / den;
        r.w = (a0.w + a1.w + a2.w + a3.w) / den;
        r.x = (r.x > 0.f) ? r.x : expm1f(r.x);
        r.y = (r.y > 0.f) ? r.y : expm1f(r.y);
        r.z = (r.z > 0.f) ? r.z : expm1f(r.z);
        r.w = (r.w > 0.f) ? r.w : expm1f(r.w);
        *(float4*)(g_h1all + (size_t)row*LDH1 + ee*HF + c0) = r;
    }
}

// batched layer-2 attention projections (float4 inner loop)
__global__ void k_s2d24(const float* __restrict__ ma2s, const float* __restrict__ ma2d,
                        const float* __restrict__ da2s, const float* __restrict__ da2d) {
    int idx = blockIdx.x*blockDim.x + threadIdx.x;
    if (idx >= 4*BS) return;
    int e   = idx / BS;
    int row = idx - e*BS;
    const float4* p  = (const float4*)(g_h2all + (size_t)row*LDH2 + e*Ddim);
    const float4* as = (const float4*)((e == 0) ? ma2s : da2s + (e-1)*Ddim);
    const float4* ad = (const float4*)((e == 0) ? ma2d : da2d + (e-1)*Ddim);
    float x = 0.f, y = 0.f;
    #pragma unroll 4
    for (int d = 0; d < Ddim/4; d++) {
        float4 v = p[d], a = as[d], dd = ad[d];
        x += v.x*a.x + v.y*a.y + v.z*a.z + v.w*a.w;
        y += v.x*dd.x + v.y*dd.y + v.z*dd.z + v.w*dd.w;
    }
    g_s2[idx] = x; g_d2[idx] = y;
}

// layer-2 sparse attention, batched: y=0 main -> g_main; y=1..3 -> g_dep3[e]
__global__ void __launch_bounds__(256) k_att2(void) {
    int row = blockIdx.x;
    int ee  = blockIdx.y;
    if (ee > 0 && g_mask[(ee-1)*BS + row] == 0.f) return;
    int b = row >> 10;
    __shared__ float sc[MAXDEG];
    __shared__ int   snbr[MAXDEG];
    __shared__ float sden;
    __shared__ __align__(16) float4 red4[4][64];
    const int* c = g_cnt + row*3;
    int lo = 0, hi;
    if      (ee == 0) hi = c[2];
    else if (ee == 1) hi = c[0];
    else if (ee == 2) { lo = c[0]; hi = c[1]; }
    else              { lo = c[1]; hi = c[2]; }
    int deg = hi - lo;
    int tid = threadIdx.x;
    float* outp = (ee == 0) ? (g_main + (size_t)row*Ddim)
                            : (g_dep3 + (size_t)(ee-1)*BSD + (size_t)row*Ddim);
    if (deg == 0) {
        for (int o = tid; o < Ddim; o += 256)
            outp[o] = g_meanh2[b*LDH2 + ee*Ddim + o];
        return;
    }
    for (int j = tid; j < deg; j += 256) snbr[j] = g_nbr[row*MAXDEG + lo + j];
    __syncthreads();
    float srcsc = g_s2[ee*BS + row];
    const float* d2b = g_d2 + ee*BS + b*Sdim;
    for (int j = tid; j < deg; j += 256) {
        float v = srcsc + d2b[snbr[j]];
        sc[j] = (v > 0.f) ? v : 0.2f*v;
    }
    __syncthreads();
    if (tid < 32) {
        float m = -1e30f;
        for (int j = tid; j < deg; j += 32) m = fmaxf(m, sc[j]);
        for (int o = 16; o; o >>= 1) m = fmaxf(m, __shfl_xor_sync(0xffffffffu, m, o));
        float su = 0.f;
        for (int j = tid; j < deg; j += 32) { float e = expf(sc[j] - m); sc[j] = e; su += e; }
        for (int o = 16; o; o >>= 1) su += __shfl_xor_sync(0xffffffffu, su, o);
        if (tid == 0) sden = su;
    }
    __syncthreads();
    int g  = tid >> 6;
    int cq = tid & 63;
    int cid = cq * 4;
    const float* hb = g_h2all + (size_t)(b*Sdim)*LDH2 + ee*Ddim + cid;
    float4 acc = make_float4(0.f, 0.f, 0.f, 0.f);
    #pragma unroll 2
    for (int j = g; j < deg; j += 4) {
        float w = sc[j];
        float4 v = *(const float4*)(hb + (size_t)snbr[j]*LDH2);
        acc.x += w*v.x; acc.y += w*v.y; acc.z += w*v.z; acc.w += w*v.w;
    }
    red4[g][cq] = acc;
    __syncthreads();
    if (tid < 64) {
        float4 a0 = red4[0][tid], a1 = red4[1][tid], a2 = red4[2][tid], a3 = red4[3][tid];
        float den = sden;
        float4 r;
        r.x = (a0.x + a1.x + a2.x + a3.x) / den;
        r.y = (a0.y + a1.y + a2.y + a3.y) / den;
        r.z = (a0.z + a1.z + a2.z + a3.z) / den;
        r.w = (a0.w + a1.w + a2.w + a3.w) / den;
        *(float4*)(outp + tid*4) = r;
    }
}

// blend + final output + deterministic partial sums of blend weights
__global__ void __launch_bounds__(256) k_final(const float* __restrict__ bbias, float* __restrict__ out) {
    __shared__ float red[256];
    int t = threadIdx.x;
    int base = blockIdx.x*1024;
    float s = 0.f;
    #pragma unroll
    for (int l = 0; l < 4; l++) {
        int i   = base + l*256 + t;
        int row = i >> 8;
        int d   = i & (Ddim-1);
        float blendv = g_hall[(size_t)row*LDH + 4*HF + d];
        float w = 1.f / (1.f + expf(-(blendv + bbias[d])));
        float dep = g_mask[0*BS + row] * g_dep3[0*BSD + i]
                  + g_mask[1*BS + row] * g_dep3[1*BSD + i]
                  + g_mask[2*BS + row] * g_dep3[2*BSD + i];
        out[i] = w*g_main[i] + (1.f - w)*dep;
        s += w;
    }
    red[t] = s; __syncthreads();
    for (int o = 128; o; o >>= 1) { if (t < o) red[t] += red[t+o]; __syncthreads(); }
    if (t == 0) g_part[blockIdx.x] = red[0];
}

__global__ void k_scalar(float* __restrict__ out) {
    __shared__ float red[256];
    int t = threadIdx.x;
    float s = 0.f;
    for (int i = t; i < 1024; i += 256) s += g_part[i];
    red[t] = s; __syncthreads();
    for (int o = 128; o; o >>= 1) { if (t < o) red[t] += red[t+o]; __syncthreads(); }
    if (t == 0) {
        float mc = red[0] / (float)BSD;
        out[BSD]     = fabsf(mc - 0.6f) * 0.01f;
        out[BSD + 1] = mc;
    }
}

// ----------------------------- host launcher -----------------------------
extern "C" void kernel_launch(void* const* d_in, const int* in_sizes, int n_in,
                              void* d_out, int out_size) {
    const float* feature = (const float*)d_in[0];
    const float* adj     = (const float*)d_in[1];
    const float* mW1     = (const float*)d_in[2];
    const float* ma1s    = (const float*)d_in[3];
    const float* ma1d    = (const float*)d_in[4];
    const float* mW2     = (const float*)d_in[5];
    const float* ma2s    = (const float*)d_in[6];
    const float* ma2d    = (const float*)d_in[7];
    const float* dW1     = (const float*)d_in[8];
    const float* da1s    = (const float*)d_in[9];
    const float* da1d    = (const float*)d_in[10];
    const float* dW2     = (const float*)d_in[11];
    const float* da2s    = (const float*)d_in[12];
    const float* da2d    = (const float*)d_in[13];
    const float* rW      = (const float*)d_in[14];
    const float* bW      = (const float*)d_in[15];
    const float* bbias   = (const float*)d_in[16];
    float* out = (float*)d_out;

    static float *p_hall = nullptr, *p_h2all, *p_meanh, *p_meanh2;
    if (!p_hall) {
        cudaGetSymbolAddress((void**)&p_hall,   g_hall);
        cudaGetSymbolAddress((void**)&p_h2all,  g_h2all);
        cudaGetSymbolAddress((void**)&p_meanh,  g_meanh);
        cudaGetSymbolAddress((void**)&p_meanh2, g_meanh2);
    }

    k_router   <<<512, 256>>>(feature, rW);
    k_build_csr<<<512, 256>>>(adj);
    k_pack     <<<(Ddim*NBIG + 255)/256, 256>>>(mW1, dW1, bW);

    // fused layer-1 (4 experts) + blend GEMM: 448 CTAs (128x128 FFMA2 tiles)
    k_gemm_big<<<dim3(NBIG/128, BS/128), 256>>>(feature);

    k_esed4  <<<(4*ESN + 255)/256, 256>>>(ma1s, ma1d, da1s, da1d);
    k_colmean<<<Bdim*(LDH1/32), 256>>>(p_hall, LDH, LDH1, p_meanh);

    k_att1<<<dim3(BS, 4), 384>>>();

    // batched layer-2 GEMM over 4 experts: 256 CTAs (128x128 FFMA2 tiles)
    k_gemm2<<<dim3(Ddim/128, BS/128, 4), 256>>>(mW2, dW2);

    k_s2d24  <<<(4*BS + 255)/256, 256>>>(ma2s, ma2d, da2s, da2d);
    k_colmean<<<Bdim*(LDH2/32), 256>>>(p_h2all, LDH2, LDH2, p_meanh2);

    k_att2<<<dim3(BS, 4), 256>>>();

    k_final<<<1024, 256>>>(bbias, out);
    if (out_size >= BSD + 2) k_scalar<<<1, 256>>>(out);
}